// round 10
// baseline (speedup 1.0000x reference)
#include <cuda_runtime.h>
#include <math.h>
#include <stdint.h>

#define Dm 1024
#define Hh 16
#define HDm 64
#define FFm 4096
#define BATCHm 8
#define SEQm 1024
#define TOKm (BATCHm*SEQm)   /* 8192 */
#define BHm (BATCHm*Hh)      /* 128  */

static __device__ float g_h   [(size_t)TOKm*Dm];
static __device__ float g_q   [(size_t)BHm*SEQm*HDm];
static __device__ float g_k   [(size_t)BHm*SEQm*HDm];
static __device__ float g_v   [(size_t)BHm*SEQm*HDm];
static __device__ float g_s   [(size_t)BHm*SEQm*SEQm]; // exp(scores)
static __device__ float g_o   [(size_t)TOKm*Dm];
static __device__ float g_x1  [(size_t)TOKm*Dm];
static __device__ float g_g   [(size_t)TOKm*FFm];

// ---------------------------------------------------------------------------
// helpers
// ---------------------------------------------------------------------------
__device__ __forceinline__ uint32_t f2tf32(float f) {
    return __float_as_uint(f);   // raw fp32 bits = RZ-truncated tf32 for HMMA
}
__device__ __forceinline__ void cp16(uint32_t dst, const void* src) {
    asm volatile("cp.async.cg.shared.global [%0], [%1], 16;" :: "r"(dst), "l"(src));
}
__device__ __forceinline__ void bulk64(uint32_t dst, const void* src, uint32_t mbar) {
    asm volatile(
        "cp.async.bulk.shared::cta.global.mbarrier::complete_tx::bytes [%0], [%1], 64, [%2];"
        :: "r"(dst), "l"(src), "r"(mbar) : "memory");
}
__device__ __forceinline__ void mbar_init(uint32_t addr, uint32_t cnt) {
    asm volatile("mbarrier.init.shared.b64 [%0], %1;" :: "r"(addr), "r"(cnt) : "memory");
}
__device__ __forceinline__ void mbar_expect_tx(uint32_t addr, uint32_t bytes) {
    asm volatile("mbarrier.arrive.expect_tx.shared.b64 _, [%0], %1;"
                 :: "r"(addr), "r"(bytes) : "memory");
}
__device__ __forceinline__ void mbar_wait(uint32_t addr, uint32_t parity) {
    asm volatile(
        "{\n\t.reg .pred P;\n\t"
        "WAIT_%=:\n\t"
        "mbarrier.try_wait.parity.acquire.cta.shared::cta.b64 P, [%0], %1, 0x989680;\n\t"
        "@P bra.uni DONE_%=;\n\t"
        "bra.uni WAIT_%=;\n\t"
        "DONE_%=:\n\t}"
        :: "r"(addr), "r"(parity) : "memory");
}
__device__ __forceinline__ void mma_tf32(float* c, const uint32_t* a, const uint32_t* b) {
    asm volatile(
        "mma.sync.aligned.m16n8k8.row.col.f32.tf32.tf32.f32 "
        "{%0,%1,%2,%3},{%4,%5,%6,%7},{%8,%9},{%0,%1,%2,%3};"
        : "+f"(c[0]), "+f"(c[1]), "+f"(c[2]), "+f"(c[3])
        : "r"(a[0]), "r"(a[1]), "r"(a[2]), "r"(a[3]), "r"(b[0]), "r"(b[1]));
}

// ---------------------------------------------------------------------------
// LayerNorm: one block per row (D=1024), 256 threads.
// ---------------------------------------------------------------------------
__global__ void ln_kernel(const float* __restrict__ x,
                          const float* __restrict__ gam,
                          const float* __restrict__ bet,
                          float* __restrict__ out)
{
    const float* xr = x + (size_t)blockIdx.x * Dm;
    float* orow     = out + (size_t)blockIdx.x * Dm;
    int tid = threadIdx.x;

    float s = 0.f, s2 = 0.f;
    for (int i = tid; i < Dm; i += 256) {
        float v = xr[i];
        s += v; s2 += v * v;
    }
    __shared__ float rs[8], rs2[8];
    #pragma unroll
    for (int o = 16; o > 0; o >>= 1) {
        s  += __shfl_xor_sync(0xffffffffu, s,  o);
        s2 += __shfl_xor_sync(0xffffffffu, s2, o);
    }
    if ((tid & 31) == 0) { rs[tid >> 5] = s; rs2[tid >> 5] = s2; }
    __syncthreads();
    if (tid < 32) {
        float a = (tid < 8) ? rs[tid]  : 0.f;
        float b = (tid < 8) ? rs2[tid] : 0.f;
        #pragma unroll
        for (int o = 4; o > 0; o >>= 1) {
            a += __shfl_xor_sync(0xffffffffu, a, o);
            b += __shfl_xor_sync(0xffffffffu, b, o);
        }
        if (tid == 0) { rs[0] = a; rs2[0] = b; }
    }
    __syncthreads();
    float mu  = rs[0] * (1.0f / Dm);
    float var = rs2[0] * (1.0f / Dm) - mu * mu;
    float inv = rsqrtf(var + 1e-5f);
    for (int i = tid; i < Dm; i += 256)
        orow[i] = (xr[i] - mu) * inv * gam[i] + bet[i];
}

// ---------------------------------------------------------------------------
// tf32 tensor-core GEMM. C[M,N] = A[M,K] @ B^T (B row-major [N,K]).
// Staging via cp.async.bulk row copies (64B/row) + mbarrier expect_tx,
// 2-stage ring. BM=BN=128, BK=16, 8 warps of 64x32.
// Batched via blockIdx.z with element strides bA/bB/bC.
// EPI: 2 bias+residual, 3 bias+exact-gelu, 5 qkv scatter (bias=qb,res=vb),
//      6 exp(store).
// ---------------------------------------------------------------------------
template<int EPI>
__global__ __launch_bounds__(256)
void tgemm(const float* __restrict__ A, const float* __restrict__ B,
           float* __restrict__ C, int M, int N, int K,
           long bA, long bB, long bC,
           const float* __restrict__ bias, const float* __restrict__ res)
{
    constexpr int BM = 128, BN = 128, BK = 16;
    constexpr int WM = 64, WN = 32;
    constexpr int MI = WM / 16, NI = WN / 8, KI = BK / 8;
    constexpr int BKP = 20;                       // 80B row stride, 16B-aligned

    __shared__ alignas(16) float As[2][BM][BKP];
    __shared__ alignas(16) float Bs[2][BN][BKP];
    __shared__ alignas(8)  uint64_t mb_store[2];

    int tid = threadIdx.x, lane = tid & 31, warp = tid >> 5;
    int wm = (warp % 2) * WM, wn = (warp / 2) * WN;
    int m0 = blockIdx.y * BM, n0 = blockIdx.x * BN;
    long z = blockIdx.z;
    const float* Ab = A + z * bA;
    const float* Bb = B + z * bB;

    uint32_t sA = (uint32_t)__cvta_generic_to_shared(&As[0][0][0]);
    uint32_t sB = (uint32_t)__cvta_generic_to_shared(&Bs[0][0][0]);
    uint32_t mb[2];
    mb[0] = (uint32_t)__cvta_generic_to_shared(&mb_store[0]);
    mb[1] = (uint32_t)__cvta_generic_to_shared(&mb_store[1]);

    if (tid == 0) { mbar_init(mb[0], 1); mbar_init(mb[1], 1); }
    __syncthreads();

    auto stage = [&](int st, int k0) {
        if (tid == 0) mbar_expect_tx(mb[st], (BM + BN) * BK * 4);
        if (tid < BM) {
            bulk64(sA + (uint32_t)(((st * BM + tid) * BKP) * 4),
                   Ab + (size_t)(m0 + tid) * K + k0, mb[st]);
        } else {
            int r = tid - BM;
            bulk64(sB + (uint32_t)(((st * BN + r) * BKP) * 4),
                   Bb + (size_t)(n0 + r) * K + k0, mb[st]);
        }
    };

    float acc[MI][NI][4] = {};
    int g = lane >> 2, tg = lane & 3;

    stage(0, 0);
    int NKT = K / BK;
    for (int kt = 0; kt < NKT; kt++) {
        int cur = kt & 1;
        if (kt + 1 < NKT) stage((kt + 1) & 1, (kt + 1) * BK);
        mbar_wait(mb[cur], (kt >> 1) & 1);

        #pragma unroll
        for (int kk = 0; kk < KI; kk++) {
            uint32_t af[MI][4];
            uint32_t bf[NI][2];
            #pragma unroll
            for (int mi = 0; mi < MI; mi++) {
                int r0 = wm + mi * 16 + g;
                af[mi][0] = f2tf32(As[cur][r0    ][kk * 8 + tg    ]);
                af[mi][1] = f2tf32(As[cur][r0 + 8][kk * 8 + tg    ]);
                af[mi][2] = f2tf32(As[cur][r0    ][kk * 8 + tg + 4]);
                af[mi][3] = f2tf32(As[cur][r0 + 8][kk * 8 + tg + 4]);
            }
            #pragma unroll
            for (int ni = 0; ni < NI; ni++) {
                int cc = wn + ni * 8 + g;
                bf[ni][0] = f2tf32(Bs[cur][cc][kk * 8 + tg    ]);
                bf[ni][1] = f2tf32(Bs[cur][cc][kk * 8 + tg + 4]);
            }
            #pragma unroll
            for (int mi = 0; mi < MI; mi++)
                #pragma unroll
                for (int ni = 0; ni < NI; ni++)
                    mma_tf32(acc[mi][ni], af[mi], bf[ni]);
        }
        __syncthreads();
    }

    // ---- epilogue ----
    #pragma unroll
    for (int mi = 0; mi < MI; mi++) {
        #pragma unroll
        for (int ni = 0; ni < NI; ni++) {
            #pragma unroll
            for (int half = 0; half < 2; half++) {
                int m = m0 + wm + mi * 16 + g + half * 8;
                float v0 = acc[mi][ni][half * 2 + 0];
                float v1 = acc[mi][ni][half * 2 + 1];
                int n = n0 + wn + ni * 8 + tg * 2;
                #pragma unroll
                for (int e = 0; e < 2; e++) {
                    float v = e ? v1 : v0;
                    int nn = n + e;
                    if (EPI == 2) {
                        C[(size_t)m * N + nn] = v + bias[nn] + res[(size_t)m * N + nn];
                    } else if (EPI == 3) {
                        float t = v + bias[nn];
                        C[(size_t)m * N + nn] =
                            0.5f * t * (1.f + erff(t * 0.70710678118654752f));
                    } else if (EPI == 5) {
                        int which = nn >> 10;
                        int r = nn & 1023;
                        int hh = r >> 6, hd = r & 63;
                        int bb = m >> 10, t = m & 1023;
                        size_t dst = (((size_t)bb * Hh + hh) * SEQm + t) * HDm + hd;
                        if (which == 0)      g_q[dst] = (v + bias[r]) * 0.125f;
                        else if (which == 1) g_k[dst] = v;
                        else                 g_v[dst] = v + res[r];
                    } else if (EPI == 6) {
                        C[z * bC + (size_t)m * N + nn] = __expf(v);
                    }
                }
            }
        }
    }
}

// ---------------------------------------------------------------------------
// attn PV: O[bh] = (P[bh] @ V[bh]) / rowsum(P[bh]); unchanged from R9.
// ---------------------------------------------------------------------------
__global__ __launch_bounds__(256, 3)
void attn_pv(const float* __restrict__ P, const float* __restrict__ V,
             float* __restrict__ O)
{
    constexpr int BM = 128, BN = 64, BK = 16;
    constexpr int BKP = BK + 4, BNP = BN + 4;
    constexpr int MI = 2, NI = 4, KI = 2;

    __shared__ float As[2][BM][BKP];
    __shared__ float Bs[2][BK][BNP];
    __shared__ float ssum[BM];

    int tid = threadIdx.x, lane = tid & 31, warp = tid >> 5;
    int g = lane >> 2, tg = lane & 3;
    int wm = (warp % 4) * 32, wn = (warp / 4) * 32;
    int m0 = blockIdx.y * BM;
    long z = blockIdx.x;
    const float* Ab = P + z * (long)SEQm * SEQm;
    const float* Bb = V + z * (long)SEQm * HDm;

    uint32_t sA = (uint32_t)__cvta_generic_to_shared(&As[0][0][0]);
    uint32_t sB = (uint32_t)__cvta_generic_to_shared(&Bs[0][0][0]);

    auto loadTile = [&](int st, int k0) {
        #pragma unroll
        for (int i = tid; i < BM * BK / 4; i += 256) {
            int r = i / (BK / 4), c = i % (BK / 4);
            uint32_t dst = sA + (uint32_t)(((st * BM + r) * BKP + c * 4) * 4);
            cp16(dst, Ab + (size_t)(m0 + r) * SEQm + k0 + c * 4);
        }
        #pragma unroll
        for (int i = tid; i < BK * BN / 4; i += 256) {
            int r = i / (BN / 4), c = i % (BN / 4);
            uint32_t dst = sB + (uint32_t)(((st * BK + r) * BNP + c * 4) * 4);
            cp16(dst, Bb + (size_t)(k0 + r) * HDm + c * 4);
        }
        asm volatile("cp.async.commit_group;");
    };

    float acc[MI][NI][4] = {};
    float rsum = 0.f;
    int srow = tid & 127, shalf = (tid >> 7) * 8;

    loadTile(0, 0);
    constexpr int NKT = SEQm / BK;
    for (int kt = 0; kt < NKT; kt++) {
        int cur = kt & 1;
        if (kt + 1 < NKT) {
            loadTile((kt + 1) & 1, (kt + 1) * BK);
            asm volatile("cp.async.wait_group 1;");
        } else {
            asm volatile("cp.async.wait_group 0;");
        }
        __syncthreads();

        {
            float4 a0 = *(const float4*)&As[cur][srow][shalf];
            float4 a1 = *(const float4*)&As[cur][srow][shalf + 4];
            rsum += (a0.x + a0.y) + (a0.z + a0.w) + (a1.x + a1.y) + (a1.z + a1.w);
        }

        #pragma unroll
        for (int kk = 0; kk < KI; kk++) {
            uint32_t af[MI][4];
            uint32_t bf[NI][2];
            #pragma unroll
            for (int mi = 0; mi < MI; mi++) {
                int r0 = wm + mi * 16 + g;
                af[mi][0] = f2tf32(As[cur][r0    ][kk * 8 + tg    ]);
                af[mi][1] = f2tf32(As[cur][r0 + 8][kk * 8 + tg    ]);
                af[mi][2] = f2tf32(As[cur][r0    ][kk * 8 + tg + 4]);
                af[mi][3] = f2tf32(As[cur][r0 + 8][kk * 8 + tg + 4]);
            }
            #pragma unroll
            for (int ni = 0; ni < NI; ni++) {
                int cc = wn + ni * 8 + g;
                bf[ni][0] = f2tf32(Bs[cur][kk * 8 + tg    ][cc]);
                bf[ni][1] = f2tf32(Bs[cur][kk * 8 + tg + 4][cc]);
            }
            #pragma unroll
            for (int mi = 0; mi < MI; mi++)
                #pragma unroll
                for (int ni = 0; ni < NI; ni++)
                    mma_tf32(acc[mi][ni], af[mi], bf[ni]);
        }
        __syncthreads();
    }

    if (tid < 128) ssum[srow] = rsum;
    __syncthreads();
    if (tid >= 128) ssum[srow] += rsum;
    __syncthreads();

    int bb = (int)(z >> 4), hh = (int)(z & 15);
    #pragma unroll
    for (int mi = 0; mi < MI; mi++) {
        #pragma unroll
        for (int half = 0; half < 2; half++) {
            int ml = wm + mi * 16 + g + half * 8;
            float inv = 1.f / ssum[ml];
            size_t base = ((size_t)bb * SEQm + m0 + ml) * Dm + hh * HDm;
            #pragma unroll
            for (int ni = 0; ni < NI; ni++) {
                int c = wn + ni * 8 + tg * 2;
                float2 w = make_float2(acc[mi][ni][half * 2 + 0] * inv,
                                       acc[mi][ni][half * 2 + 1] * inv);
                *(float2*)&O[base + c] = w;
            }
        }
    }
}

// ---------------------------------------------------------------------------
extern "C" void kernel_launch(void* const* d_in, const int* in_sizes, int n_in,
                              void* d_out, int out_size)
{
    const float* x      = (const float*)d_in[0];
    const float* ln1_g  = (const float*)d_in[1];
    const float* ln1_b  = (const float*)d_in[2];
    const float* ln2_g  = (const float*)d_in[3];
    const float* ln2_b  = (const float*)d_in[4];
    const float* qkv_w  = (const float*)d_in[5];
    const float* q_bias = (const float*)d_in[6];
    const float* v_bias = (const float*)d_in[7];
    const float* proj_w = (const float*)d_in[8];
    const float* proj_b = (const float*)d_in[9];
    const float* fc1_w  = (const float*)d_in[10];
    const float* fc1_b  = (const float*)d_in[11];
    const float* fc2_w  = (const float*)d_in[12];
    const float* fc2_b  = (const float*)d_in[13];
    float* out = (float*)d_out;

    float *h, *q, *k, *v, *s, *o, *x1, *g;
    cudaGetSymbolAddress((void**)&h,  g_h);
    cudaGetSymbolAddress((void**)&q,  g_q);
    cudaGetSymbolAddress((void**)&k,  g_k);
    cudaGetSymbolAddress((void**)&v,  g_v);
    cudaGetSymbolAddress((void**)&s,  g_s);
    cudaGetSymbolAddress((void**)&o,  g_o);
    cudaGetSymbolAddress((void**)&x1, g_x1);
    cudaGetSymbolAddress((void**)&g,  g_g);

    // 1. LN1
    ln_kernel<<<TOKm, 256>>>(x, ln1_g, ln1_b, h);

    // 2. QKV = h @ qkv_w^T, fused scatter to q/k/v [B,H,N,HD] + biases + q-scale
    tgemm<5><<<dim3(3072/128, TOKm/128, 1), 256>>>(
        h, qkv_w, nullptr, TOKm, 3*Dm, Dm, 0, 0, 0, q_bias, v_bias);

    // 3. expS[bh] = exp(q[bh] @ k[bh]^T)  (K=64; exp fused in epilogue)
    tgemm<6><<<dim3(SEQm/128, SEQm/128, BHm), 256>>>(
        q, k, s, SEQm, SEQm, HDm,
        (long)SEQm*HDm, (long)SEQm*HDm, (long)SEQm*SEQm, nullptr, nullptr);

    // 4. o = (expS @ v) / rowsum(expS), scattered to [b,t,(h,hd)]
    attn_pv<<<dim3(BHm, SEQm/128), 256>>>(s, v, o);

    // 5. x1 = x + o @ proj_w^T + proj_b
    tgemm<2><<<dim3(Dm/128, TOKm/128, 1), 256>>>(
        o, proj_w, x1, TOKm, Dm, Dm, 0, 0, 0, proj_b, x);

    // 6. LN2
    ln_kernel<<<TOKm, 256>>>(x1, ln2_g, ln2_b, h);

    // 7. g = gelu(h @ fc1_w^T + fc1_b)
    tgemm<3><<<dim3(FFm/128, TOKm/128, 1), 256>>>(
        h, fc1_w, g, TOKm, FFm, Dm, 0, 0, 0, fc1_b, nullptr);

    // 8. out = x1 + g @ fc2_w^T + fc2_b
    tgemm<2><<<dim3(Dm/128, TOKm/128, 1), 256>>>(
        g, fc2_w, out, TOKm, Dm, FFm, 0, 0, 0, fc2_b, x1);
}

// round 11
// speedup vs baseline: 1.7094x; 1.7094x over previous
#include <cuda_runtime.h>
#include <math.h>
#include <stdint.h>

#define Dm 1024
#define Hh 16
#define HDm 64
#define FFm 4096
#define BATCHm 8
#define SEQm 1024
#define TOKm (BATCHm*SEQm)   /* 8192 */
#define BHm (BATCHm*Hh)      /* 128  */

static __device__ float g_h   [(size_t)TOKm*Dm];
static __device__ float g_q   [(size_t)BHm*SEQm*HDm];
static __device__ float g_k   [(size_t)BHm*SEQm*HDm];
static __device__ float g_v   [(size_t)BHm*SEQm*HDm];
static __device__ float g_s   [(size_t)BHm*SEQm*SEQm]; // exp(scores)
static __device__ float g_o   [(size_t)TOKm*Dm];
static __device__ float g_x1  [(size_t)TOKm*Dm];
static __device__ float g_g   [(size_t)TOKm*FFm];

// ---------------------------------------------------------------------------
// helpers
// ---------------------------------------------------------------------------
__device__ __forceinline__ uint32_t f2tf32(float f) {
    return __float_as_uint(f);   // raw fp32 bits = RZ-truncated tf32 for HMMA
}
__device__ __forceinline__ void cp16(uint32_t dst, const void* src) {
    asm volatile("cp.async.cg.shared.global [%0], [%1], 16;" :: "r"(dst), "l"(src));
}
__device__ __forceinline__ void mma_tf32(float* c, const uint32_t* a, const uint32_t* b) {
    asm volatile(
        "mma.sync.aligned.m16n8k8.row.col.f32.tf32.tf32.f32 "
        "{%0,%1,%2,%3},{%4,%5,%6,%7},{%8,%9},{%0,%1,%2,%3};"
        : "+f"(c[0]), "+f"(c[1]), "+f"(c[2]), "+f"(c[3])
        : "r"(a[0]), "r"(a[1]), "r"(a[2]), "r"(a[3]), "r"(b[0]), "r"(b[1]));
}

// ---------------------------------------------------------------------------
// LayerNorm: one block per row (D=1024), 256 threads.
// ---------------------------------------------------------------------------
__global__ void ln_kernel(const float* __restrict__ x,
                          const float* __restrict__ gam,
                          const float* __restrict__ bet,
                          float* __restrict__ out)
{
    const float* xr = x + (size_t)blockIdx.x * Dm;
    float* orow     = out + (size_t)blockIdx.x * Dm;
    int tid = threadIdx.x;

    float s = 0.f, s2 = 0.f;
    for (int i = tid; i < Dm; i += 256) {
        float v = xr[i];
        s += v; s2 += v * v;
    }
    __shared__ float rs[8], rs2[8];
    #pragma unroll
    for (int o = 16; o > 0; o >>= 1) {
        s  += __shfl_xor_sync(0xffffffffu, s,  o);
        s2 += __shfl_xor_sync(0xffffffffu, s2, o);
    }
    if ((tid & 31) == 0) { rs[tid >> 5] = s; rs2[tid >> 5] = s2; }
    __syncthreads();
    if (tid < 32) {
        float a = (tid < 8) ? rs[tid]  : 0.f;
        float b = (tid < 8) ? rs2[tid] : 0.f;
        #pragma unroll
        for (int o = 4; o > 0; o >>= 1) {
            a += __shfl_xor_sync(0xffffffffu, a, o);
            b += __shfl_xor_sync(0xffffffffu, b, o);
        }
        if (tid == 0) { rs[0] = a; rs2[0] = b; }
    }
    __syncthreads();
    float mu  = rs[0] * (1.0f / Dm);
    float var = rs2[0] * (1.0f / Dm) - mu * mu;
    float inv = rsqrtf(var + 1e-5f);
    for (int i = tid; i < Dm; i += 256)
        orow[i] = (xr[i] - mu) * inv * gam[i] + bet[i];
}

// ---------------------------------------------------------------------------
// tf32 tensor-core GEMM. C[M,N] = A[M,K] @ B^T (B row-major [N,K]).
// cp.async 16B staging into a 3-stage ring (16KB/stage, 48KB total).
// No padding: SW64-style XOR swizzle (16B chunk ^ (row>>1)) — verified
// conflict-free for all fragment read patterns.
// Batched via blockIdx.z with element strides bA/bB/bC.
// EPI: 2 bias+residual, 3 bias+exact-gelu, 5 qkv scatter (bias=qb,res=vb),
//      6 exp(store).
// ---------------------------------------------------------------------------
template<int EPI>
__global__ __launch_bounds__(256)
void tgemm(const float* __restrict__ A, const float* __restrict__ B,
           float* __restrict__ C, int M, int N, int K,
           long bA, long bB, long bC,
           const float* __restrict__ bias, const float* __restrict__ res)
{
    constexpr int BM = 128, BN = 128, BK = 16;
    constexpr int WM = 64, WN = 32;
    constexpr int MI = WM / 16, NI = WN / 8, KI = BK / 8;
    constexpr int STAGES = 3;
    constexpr int TILE = BM * BK;               // 2048 floats per operand stage

    __shared__ alignas(1024) float As[STAGES][TILE];
    __shared__ alignas(1024) float Bs[STAGES][TILE];

    int tid = threadIdx.x, lane = tid & 31, warp = tid >> 5;
    int wm = (warp % 2) * WM, wn = (warp / 2) * WN;
    int m0 = blockIdx.y * BM, n0 = blockIdx.x * BN;
    long z = blockIdx.z;
    const float* Ab = A + z * bA;
    const float* Bb = B + z * bB;

    uint32_t sA = (uint32_t)__cvta_generic_to_shared(&As[0][0]);
    uint32_t sB = (uint32_t)__cvta_generic_to_shared(&Bs[0][0]);

    // swizzled write index (float units): row r, 16B chunk c4 (0..3)
    auto widx = [](int r, int c4) {
        return r * BK + ((c4 ^ ((r & 6) >> 1)) << 2);
    };

    auto stage = [&](int st, int k0) {
        #pragma unroll
        for (int i = tid; i < TILE / 4; i += 256) {
            int r = i >> 2, c4 = i & 3;
            cp16(sA + (uint32_t)((st * TILE + widx(r, c4)) * 4),
                 Ab + (size_t)(m0 + r) * K + k0 + c4 * 4);
        }
        #pragma unroll
        for (int i = tid; i < TILE / 4; i += 256) {
            int r = i >> 2, c4 = i & 3;
            cp16(sB + (uint32_t)((st * TILE + widx(r, c4)) * 4),
                 Bb + (size_t)(n0 + r) * K + k0 + c4 * 4);
        }
        asm volatile("cp.async.commit_group;");
    };

    float acc[MI][NI][4] = {};
    int g = lane >> 2, tg = lane & 3;
    int sr = g >> 1;                            // swizzle selector for this lane

    int NKT = K / BK;
    stage(0, 0);
    stage(1, BK);
    for (int kt = 0; kt < NKT; kt++) {
        int cur = kt % STAGES;
        if (kt + 2 < NKT) stage((kt + 2) % STAGES, (kt + 2) * BK);
        else              asm volatile("cp.async.commit_group;");   // keep group count
        asm volatile("cp.async.wait_group 2;");
        __syncthreads();

        const float* Ac = As[cur];
        const float* Bc = Bs[cur];
        #pragma unroll
        for (int kk = 0; kk < KI; kk++) {
            int c0 = (((2 * kk    ) ^ sr) << 2) + tg;   // cols kk*8+tg
            int c1 = (((2 * kk + 1) ^ sr) << 2) + tg;   // cols kk*8+tg+4
            uint32_t af[MI][4];
            uint32_t bf[NI][2];
            #pragma unroll
            for (int mi = 0; mi < MI; mi++) {
                int r0 = (wm + mi * 16 + g) * BK;
                af[mi][0] = f2tf32(Ac[r0            + c0]);
                af[mi][1] = f2tf32(Ac[r0 + 8 * BK   + c0]);
                af[mi][2] = f2tf32(Ac[r0            + c1]);
                af[mi][3] = f2tf32(Ac[r0 + 8 * BK   + c1]);
            }
            #pragma unroll
            for (int ni = 0; ni < NI; ni++) {
                int rb = (wn + ni * 8 + g) * BK;
                bf[ni][0] = f2tf32(Bc[rb + c0]);
                bf[ni][1] = f2tf32(Bc[rb + c1]);
            }
            #pragma unroll
            for (int mi = 0; mi < MI; mi++)
                #pragma unroll
                for (int ni = 0; ni < NI; ni++)
                    mma_tf32(acc[mi][ni], af[mi], bf[ni]);
        }
        __syncthreads();
    }

    // ---- epilogue ----
    #pragma unroll
    for (int mi = 0; mi < MI; mi++) {
        #pragma unroll
        for (int ni = 0; ni < NI; ni++) {
            #pragma unroll
            for (int half = 0; half < 2; half++) {
                int m = m0 + wm + mi * 16 + g + half * 8;
                float v0 = acc[mi][ni][half * 2 + 0];
                float v1 = acc[mi][ni][half * 2 + 1];
                int n = n0 + wn + ni * 8 + tg * 2;
                #pragma unroll
                for (int e = 0; e < 2; e++) {
                    float v = e ? v1 : v0;
                    int nn = n + e;
                    if (EPI == 2) {
                        C[(size_t)m * N + nn] = v + bias[nn] + res[(size_t)m * N + nn];
                    } else if (EPI == 3) {
                        float t = v + bias[nn];
                        C[(size_t)m * N + nn] =
                            0.5f * t * (1.f + erff(t * 0.70710678118654752f));
                    } else if (EPI == 5) {
                        int which = nn >> 10;
                        int r = nn & 1023;
                        int hh = r >> 6, hd = r & 63;
                        int bb = m >> 10, t = m & 1023;
                        size_t dst = (((size_t)bb * Hh + hh) * SEQm + t) * HDm + hd;
                        if (which == 0)      g_q[dst] = (v + bias[r]) * 0.125f;
                        else if (which == 1) g_k[dst] = v;
                        else                 g_v[dst] = v + res[r];
                    } else if (EPI == 6) {
                        C[z * bC + (size_t)m * N + nn] = __expf(v);
                    }
                }
            }
        }
    }
}

// ---------------------------------------------------------------------------
// attn PV: O[bh] = (P[bh] @ V[bh]) / rowsum(P[bh]); unchanged (near DRAM bound).
// ---------------------------------------------------------------------------
__global__ __launch_bounds__(256, 3)
void attn_pv(const float* __restrict__ P, const float* __restrict__ V,
             float* __restrict__ O)
{
    constexpr int BM = 128, BN = 64, BK = 16;
    constexpr int BKP = BK + 4, BNP = BN + 4;
    constexpr int MI = 2, NI = 4, KI = 2;

    __shared__ float As[2][BM][BKP];
    __shared__ float Bs[2][BK][BNP];
    __shared__ float ssum[BM];

    int tid = threadIdx.x, lane = tid & 31, warp = tid >> 5;
    int g = lane >> 2, tg = lane & 3;
    int wm = (warp % 4) * 32, wn = (warp / 4) * 32;
    int m0 = blockIdx.y * BM;
    long z = blockIdx.x;
    const float* Ab = P + z * (long)SEQm * SEQm;
    const float* Bb = V + z * (long)SEQm * HDm;

    uint32_t sA = (uint32_t)__cvta_generic_to_shared(&As[0][0][0]);
    uint32_t sB = (uint32_t)__cvta_generic_to_shared(&Bs[0][0][0]);

    auto loadTile = [&](int st, int k0) {
        #pragma unroll
        for (int i = tid; i < BM * BK / 4; i += 256) {
            int r = i / (BK / 4), c = i % (BK / 4);
            uint32_t dst = sA + (uint32_t)(((st * BM + r) * BKP + c * 4) * 4);
            cp16(dst, Ab + (size_t)(m0 + r) * SEQm + k0 + c * 4);
        }
        #pragma unroll
        for (int i = tid; i < BK * BN / 4; i += 256) {
            int r = i / (BN / 4), c = i % (BN / 4);
            uint32_t dst = sB + (uint32_t)(((st * BK + r) * BNP + c * 4) * 4);
            cp16(dst, Bb + (size_t)(k0 + r) * HDm + c * 4);
        }
        asm volatile("cp.async.commit_group;");
    };

    float acc[MI][NI][4] = {};
    float rsum = 0.f;
    int srow = tid & 127, shalf = (tid >> 7) * 8;

    loadTile(0, 0);
    constexpr int NKT = SEQm / BK;
    for (int kt = 0; kt < NKT; kt++) {
        int cur = kt & 1;
        if (kt + 1 < NKT) {
            loadTile((kt + 1) & 1, (kt + 1) * BK);
            asm volatile("cp.async.wait_group 1;");
        } else {
            asm volatile("cp.async.wait_group 0;");
        }
        __syncthreads();

        {
            float4 a0 = *(const float4*)&As[cur][srow][shalf];
            float4 a1 = *(const float4*)&As[cur][srow][shalf + 4];
            rsum += (a0.x + a0.y) + (a0.z + a0.w) + (a1.x + a1.y) + (a1.z + a1.w);
        }

        #pragma unroll
        for (int kk = 0; kk < KI; kk++) {
            uint32_t af[MI][4];
            uint32_t bf[NI][2];
            #pragma unroll
            for (int mi = 0; mi < MI; mi++) {
                int r0 = wm + mi * 16 + g;
                af[mi][0] = f2tf32(As[cur][r0    ][kk * 8 + tg    ]);
                af[mi][1] = f2tf32(As[cur][r0 + 8][kk * 8 + tg    ]);
                af[mi][2] = f2tf32(As[cur][r0    ][kk * 8 + tg + 4]);
                af[mi][3] = f2tf32(As[cur][r0 + 8][kk * 8 + tg + 4]);
            }
            #pragma unroll
            for (int ni = 0; ni < NI; ni++) {
                int cc = wn + ni * 8 + g;
                bf[ni][0] = f2tf32(Bs[cur][kk * 8 + tg    ][cc]);
                bf[ni][1] = f2tf32(Bs[cur][kk * 8 + tg + 4][cc]);
            }
            #pragma unroll
            for (int mi = 0; mi < MI; mi++)
                #pragma unroll
                for (int ni = 0; ni < NI; ni++)
                    mma_tf32(acc[mi][ni], af[mi], bf[ni]);
        }
        __syncthreads();
    }

    if (tid < 128) ssum[srow] = rsum;
    __syncthreads();
    if (tid >= 128) ssum[srow] += rsum;
    __syncthreads();

    int bb = (int)(z >> 4), hh = (int)(z & 15);
    #pragma unroll
    for (int mi = 0; mi < MI; mi++) {
        #pragma unroll
        for (int half = 0; half < 2; half++) {
            int ml = wm + mi * 16 + g + half * 8;
            float inv = 1.f / ssum[ml];
            size_t base = ((size_t)bb * SEQm + m0 + ml) * Dm + hh * HDm;
            #pragma unroll
            for (int ni = 0; ni < NI; ni++) {
                int c = wn + ni * 8 + tg * 2;
                float2 w = make_float2(acc[mi][ni][half * 2 + 0] * inv,
                                       acc[mi][ni][half * 2 + 1] * inv);
                *(float2*)&O[base + c] = w;
            }
        }
    }
}

// ---------------------------------------------------------------------------
extern "C" void kernel_launch(void* const* d_in, const int* in_sizes, int n_in,
                              void* d_out, int out_size)
{
    const float* x      = (const float*)d_in[0];
    const float* ln1_g  = (const float*)d_in[1];
    const float* ln1_b  = (const float*)d_in[2];
    const float* ln2_g  = (const float*)d_in[3];
    const float* ln2_b  = (const float*)d_in[4];
    const float* qkv_w  = (const float*)d_in[5];
    const float* q_bias = (const float*)d_in[6];
    const float* v_bias = (const float*)d_in[7];
    const float* proj_w = (const float*)d_in[8];
    const float* proj_b = (const float*)d_in[9];
    const float* fc1_w  = (const float*)d_in[10];
    const float* fc1_b  = (const float*)d_in[11];
    const float* fc2_w  = (const float*)d_in[12];
    const float* fc2_b  = (const float*)d_in[13];
    float* out = (float*)d_out;

    float *h, *q, *k, *v, *s, *o, *x1, *g;
    cudaGetSymbolAddress((void**)&h,  g_h);
    cudaGetSymbolAddress((void**)&q,  g_q);
    cudaGetSymbolAddress((void**)&k,  g_k);
    cudaGetSymbolAddress((void**)&v,  g_v);
    cudaGetSymbolAddress((void**)&s,  g_s);
    cudaGetSymbolAddress((void**)&o,  g_o);
    cudaGetSymbolAddress((void**)&x1, g_x1);
    cudaGetSymbolAddress((void**)&g,  g_g);

    // 1. LN1
    ln_kernel<<<TOKm, 256>>>(x, ln1_g, ln1_b, h);

    // 2. QKV = h @ qkv_w^T, fused scatter to q/k/v [B,H,N,HD] + biases + q-scale
    tgemm<5><<<dim3(3072/128, TOKm/128, 1), 256>>>(
        h, qkv_w, nullptr, TOKm, 3*Dm, Dm, 0, 0, 0, q_bias, v_bias);

    // 3. expS[bh] = exp(q[bh] @ k[bh]^T)  (K=64; exp fused in epilogue)
    tgemm<6><<<dim3(SEQm/128, SEQm/128, BHm), 256>>>(
        q, k, s, SEQm, SEQm, HDm,
        (long)SEQm*HDm, (long)SEQm*HDm, (long)SEQm*SEQm, nullptr, nullptr);

    // 4. o = (expS @ v) / rowsum(expS), scattered to [b,t,(h,hd)]
    attn_pv<<<dim3(BHm, SEQm/128), 256>>>(s, v, o);

    // 5. x1 = x + o @ proj_w^T + proj_b
    tgemm<2><<<dim3(Dm/128, TOKm/128, 1), 256>>>(
        o, proj_w, x1, TOKm, Dm, Dm, 0, 0, 0, proj_b, x);

    // 6. LN2
    ln_kernel<<<TOKm, 256>>>(x1, ln2_g, ln2_b, h);

    // 7. g = gelu(h @ fc1_w^T + fc1_b)
    tgemm<3><<<dim3(FFm/128, TOKm/128, 1), 256>>>(
        h, fc1_w, g, TOKm, FFm, Dm, 0, 0, 0, fc1_b, nullptr);

    // 8. out = x1 + g @ fc2_w^T + fc2_b
    tgemm<2><<<dim3(Dm/128, TOKm/128, 1), 256>>>(
        g, fc2_w, out, TOKm, Dm, FFm, 0, 0, 0, fc2_b, x1);
}

// round 12
// speedup vs baseline: 1.8376x; 1.0749x over previous
#include <cuda_runtime.h>
#include <cuda_bf16.h>
#include <math.h>
#include <stdint.h>

#define Dm 1024
#define Hh 16
#define HDm 64
#define FFm 4096
#define BATCHm 8
#define SEQm 1024
#define TOKm (BATCHm*SEQm)   /* 8192 */
#define BHm (BATCHm*Hh)      /* 128  */

static __device__ __nv_bfloat16 g_hb [(size_t)TOKm*Dm];
static __device__ __nv_bfloat16 g_qb [(size_t)BHm*SEQm*HDm];
static __device__ __nv_bfloat16 g_kb [(size_t)BHm*SEQm*HDm];
static __device__ __nv_bfloat16 g_vtb[(size_t)BHm*SEQm*HDm];   // [bh, hd, t]
static __device__ __nv_bfloat16 g_sb [(size_t)BHm*SEQm*SEQm];  // exp(scores) bf16
static __device__ __nv_bfloat16 g_ob [(size_t)TOKm*Dm];
static __device__ __nv_bfloat16 g_gb [(size_t)TOKm*FFm];
static __device__ float         g_x1 [(size_t)TOKm*Dm];
static __device__ __nv_bfloat16 w_qkv[(size_t)3*Dm*Dm];
static __device__ __nv_bfloat16 w_proj[(size_t)Dm*Dm];
static __device__ __nv_bfloat16 w_fc1[(size_t)FFm*Dm];
static __device__ __nv_bfloat16 w_fc2[(size_t)Dm*FFm];

// ---------------------------------------------------------------------------
// helpers
// ---------------------------------------------------------------------------
__device__ __forceinline__ void cp16(uint32_t dst, const void* src) {
    asm volatile("cp.async.cg.shared.global [%0], [%1], 16;" :: "r"(dst), "l"(src));
}
__device__ __forceinline__ void mma_bf16(float* c, const uint32_t* a, const uint32_t* b) {
    asm volatile(
        "mma.sync.aligned.m16n8k16.row.col.f32.bf16.bf16.f32 "
        "{%0,%1,%2,%3},{%4,%5,%6,%7},{%8,%9},{%0,%1,%2,%3};"
        : "+f"(c[0]), "+f"(c[1]), "+f"(c[2]), "+f"(c[3])
        : "r"(a[0]), "r"(a[1]), "r"(a[2]), "r"(a[3]), "r"(b[0]), "r"(b[1]));
}
__device__ __forceinline__ uint32_t packbf(float lo, float hi) {
    uint32_t r;
    asm("cvt.rn.bf16x2.f32 %0, %1, %2;" : "=r"(r) : "f"(hi), "f"(lo));
    return r;
}

// ---------------------------------------------------------------------------
// fp32 -> bf16 conversion (weights)
// ---------------------------------------------------------------------------
__global__ void cvt_kernel(const float* __restrict__ src,
                           __nv_bfloat16* __restrict__ dst, int n)
{
    int i = blockIdx.x * 256 + threadIdx.x;
    if (i < n) dst[i] = __float2bfloat16_rn(src[i]);
}

// ---------------------------------------------------------------------------
// LayerNorm: fp32 in, bf16 out. One block per row (D=1024).
// ---------------------------------------------------------------------------
__global__ void ln_kernel(const float* __restrict__ x,
                          const float* __restrict__ gam,
                          const float* __restrict__ bet,
                          __nv_bfloat16* __restrict__ out)
{
    const float* xr = x + (size_t)blockIdx.x * Dm;
    __nv_bfloat16* orow = out + (size_t)blockIdx.x * Dm;
    int tid = threadIdx.x;

    float s = 0.f, s2 = 0.f;
    for (int i = tid; i < Dm; i += 256) {
        float v = xr[i];
        s += v; s2 += v * v;
    }
    __shared__ float rs[8], rs2[8];
    #pragma unroll
    for (int o = 16; o > 0; o >>= 1) {
        s  += __shfl_xor_sync(0xffffffffu, s,  o);
        s2 += __shfl_xor_sync(0xffffffffu, s2, o);
    }
    if ((tid & 31) == 0) { rs[tid >> 5] = s; rs2[tid >> 5] = s2; }
    __syncthreads();
    if (tid < 32) {
        float a = (tid < 8) ? rs[tid]  : 0.f;
        float b = (tid < 8) ? rs2[tid] : 0.f;
        #pragma unroll
        for (int o = 4; o > 0; o >>= 1) {
            a += __shfl_xor_sync(0xffffffffu, a, o);
            b += __shfl_xor_sync(0xffffffffu, b, o);
        }
        if (tid == 0) { rs[0] = a; rs2[0] = b; }
    }
    __syncthreads();
    float mu  = rs[0] * (1.0f / Dm);
    float var = rs2[0] * (1.0f / Dm) - mu * mu;
    float inv = rsqrtf(var + 1e-5f);
    for (int i = tid; i < Dm; i += 256)
        orow[i] = __float2bfloat16_rn((xr[i] - mu) * inv * gam[i] + bet[i]);
}

// ---------------------------------------------------------------------------
// bf16 tensor-core GEMM. C = A[M,K] @ B^T (both bf16 row-major K-major).
// BM=BN=128, BK=32, 3-stage cp.async ring (48KB), XOR swizzle (16B chunks).
// EPI: 2 fp32 bias+residual, 3 bf16 bias+gelu, 5 qkv scatter, 6 bf16 exp.
// ---------------------------------------------------------------------------
template<int EPI>
__global__ __launch_bounds__(256)
void tgemm(const __nv_bfloat16* __restrict__ A, const __nv_bfloat16* __restrict__ B,
           float* __restrict__ C, int M, int N, int K,
           long bA, long bB, long bC,
           const float* __restrict__ bias, const float* __restrict__ res)
{
    constexpr int BM = 128, BN = 128, BK = 32;
    constexpr int MI = 4, NI = 4;               // WM=64, WN=32, 8 warps
    constexpr int STAGES = 3;
    constexpr int TILE32 = BM * 16;             // 2048 u32 per operand stage

    __shared__ alignas(1024) uint32_t As32[STAGES * TILE32];
    __shared__ alignas(1024) uint32_t Bs32[STAGES * TILE32];

    int tid = threadIdx.x, lane = tid & 31, warp = tid >> 5;
    int g = lane >> 2, tg = lane & 3;
    int wm = (warp % 2) * 64, wn = (warp / 2) * 32;
    int m0 = blockIdx.y * BM, n0 = blockIdx.x * BN;
    long z = blockIdx.z;
    const __nv_bfloat16* Ab = A + z * bA;
    const __nv_bfloat16* Bb = B + z * bB;

    uint32_t sA = (uint32_t)__cvta_generic_to_shared(&As32[0]);
    uint32_t sB = (uint32_t)__cvta_generic_to_shared(&Bs32[0]);

    auto stage = [&](int st, int k0) {
        #pragma unroll
        for (int i = tid; i < 512; i += 256) {
            int r = i >> 2, c = i & 3;
            cp16(sA + (uint32_t)((st * TILE32 + r * 16 + ((c ^ ((r >> 1) & 3)) << 2)) * 4),
                 Ab + (size_t)(m0 + r) * K + k0 + c * 8);
        }
        #pragma unroll
        for (int i = tid; i < 512; i += 256) {
            int r = i >> 2, c = i & 3;
            cp16(sB + (uint32_t)((st * TILE32 + r * 16 + ((c ^ ((r >> 1) & 3)) << 2)) * 4),
                 Bb + (size_t)(n0 + r) * K + k0 + c * 8);
        }
        asm volatile("cp.async.commit_group;");
    };

    float acc[MI][NI][4] = {};
    int swa = ((wm + g) >> 1) & 3;
    int swb = ((wn + g) >> 1) & 3;

    int NKT = K / BK;
    stage(0, 0);
    stage(1, BK);
    for (int kt = 0; kt < NKT; kt++) {
        int cur = kt % STAGES;
        if (kt + 2 < NKT) stage((kt + 2) % STAGES, (kt + 2) * BK);
        else              asm volatile("cp.async.commit_group;");
        asm volatile("cp.async.wait_group 2;");
        __syncthreads();

        const uint32_t* Ac = &As32[cur * TILE32];
        const uint32_t* Bc = &Bs32[cur * TILE32];
        #pragma unroll
        for (int kk = 0; kk < 2; kk++) {
            int p0 = (((kk * 2    ) ^ swa) << 2) | tg;
            int p1 = (((kk * 2 + 1) ^ swa) << 2) | tg;
            int q0 = (((kk * 2    ) ^ swb) << 2) | tg;
            int q1 = (((kk * 2 + 1) ^ swb) << 2) | tg;
            uint32_t af[MI][4];
            uint32_t bf[NI][2];
            #pragma unroll
            for (int mi = 0; mi < MI; mi++) {
                int ra = (wm + mi * 16 + g) * 16;
                af[mi][0] = Ac[ra       + p0];
                af[mi][1] = Ac[ra + 128 + p0];
                af[mi][2] = Ac[ra       + p1];
                af[mi][3] = Ac[ra + 128 + p1];
            }
            #pragma unroll
            for (int ni = 0; ni < NI; ni++) {
                int rb = (wn + ni * 8 + g) * 16;
                bf[ni][0] = Bc[rb + q0];
                bf[ni][1] = Bc[rb + q1];
            }
            #pragma unroll
            for (int mi = 0; mi < MI; mi++)
                #pragma unroll
                for (int ni = 0; ni < NI; ni++)
                    mma_bf16(acc[mi][ni], af[mi], bf[ni]);
        }
        __syncthreads();
    }

    // ---- epilogue ----
    #pragma unroll
    for (int mi = 0; mi < MI; mi++) {
        #pragma unroll
        for (int ni = 0; ni < NI; ni++) {
            #pragma unroll
            for (int half = 0; half < 2; half++) {
                int m = m0 + wm + mi * 16 + g + half * 8;
                float v0 = acc[mi][ni][half * 2 + 0];
                float v1 = acc[mi][ni][half * 2 + 1];
                int n = n0 + wn + ni * 8 + tg * 2;
                if (EPI == 2) {
                    float2 w;
                    w.x = v0 + bias[n    ] + res[(size_t)m * N + n    ];
                    w.y = v1 + bias[n + 1] + res[(size_t)m * N + n + 1];
                    *(float2*)&C[(size_t)m * N + n] = w;
                } else if (EPI == 3) {
                    float t0 = v0 + bias[n], t1 = v1 + bias[n + 1];
                    t0 = 0.5f * t0 * (1.f + erff(t0 * 0.70710678118654752f));
                    t1 = 0.5f * t1 * (1.f + erff(t1 * 0.70710678118654752f));
                    ((uint32_t*)C)[((size_t)m * N + n) >> 1] = packbf(t0, t1);
                } else if (EPI == 6) {
                    ((uint32_t*)C)[(z * bC + (size_t)m * N + n) >> 1] =
                        packbf(__expf(v0), __expf(v1));
                } else if (EPI == 5) {
                    #pragma unroll
                    for (int e = 0; e < 2; e++) {
                        float v = e ? v1 : v0;
                        int nn = n + e;
                        int which = nn >> 10;
                        int r = nn & 1023;
                        int hh = r >> 6, hd = r & 63;
                        int bb = m >> 10, t = m & 1023;
                        int bh = bb * Hh + hh;
                        if (which == 0)
                            g_qb[((size_t)bh * SEQm + t) * HDm + hd] =
                                __float2bfloat16_rn((v + bias[r]) * 0.125f);
                        else if (which == 1)
                            g_kb[((size_t)bh * SEQm + t) * HDm + hd] =
                                __float2bfloat16_rn(v);
                        else
                            g_vtb[((size_t)bh * HDm + hd) * SEQm + t] =
                                __float2bfloat16_rn(v + res[r]);
                    }
                }
            }
        }
    }
}

// ---------------------------------------------------------------------------
// attn PV: O[bh] = (P @ Vt^T) / rowsum(P). P bf16 [SEQ,SEQ], Vt bf16 [HD,SEQ].
// Same bf16 TB-GEMM pattern, BM=128 BN=64 BK=32, 3-stage ring. Row sums
// accumulated fp32 from the staged P tiles in fixed order (deterministic).
// Output bf16 packed, scattered to [b, t, (h,hd)].
// ---------------------------------------------------------------------------
__global__ __launch_bounds__(256)
void attn_pv(const __nv_bfloat16* __restrict__ P, const __nv_bfloat16* __restrict__ V,
             __nv_bfloat16* __restrict__ O)
{
    constexpr int BM = 128, BN = 64, BK = 32;
    constexpr int MI = 2, NI = 4;               // WM=32, WN=32; 4x2 warps
    constexpr int STAGES = 3;
    constexpr int TA32 = BM * 16;               // 2048
    constexpr int TB32 = BN * 16;               // 1024

    __shared__ alignas(1024) uint32_t As32[STAGES * TA32];
    __shared__ alignas(1024) uint32_t Bs32[STAGES * TB32];
    __shared__ float ssum[BM];

    int tid = threadIdx.x, lane = tid & 31, warp = tid >> 5;
    int g = lane >> 2, tg = lane & 3;
    int wm = (warp % 4) * 32, wn = (warp / 4) * 32;
    int m0 = blockIdx.y * BM;
    long z = blockIdx.x;
    const __nv_bfloat16* Ab = P + z * (long)SEQm * SEQm;
    const __nv_bfloat16* Bb = V + z * (long)SEQm * HDm;

    uint32_t sA = (uint32_t)__cvta_generic_to_shared(&As32[0]);
    uint32_t sB = (uint32_t)__cvta_generic_to_shared(&Bs32[0]);

    auto stage = [&](int st, int k0) {
        #pragma unroll
        for (int i = tid; i < 512; i += 256) {
            int r = i >> 2, c = i & 3;
            cp16(sA + (uint32_t)((st * TA32 + r * 16 + ((c ^ ((r >> 1) & 3)) << 2)) * 4),
                 Ab + (size_t)(m0 + r) * SEQm + k0 + c * 8);
        }
        {
            int i = tid;
            if (i < 256) {
                int r = i >> 2, c = i & 3;
                cp16(sB + (uint32_t)((st * TB32 + r * 16 + ((c ^ ((r >> 1) & 3)) << 2)) * 4),
                     Bb + (size_t)r * SEQm + k0 + c * 8);
            }
        }
        asm volatile("cp.async.commit_group;");
    };

    float acc[MI][NI][4] = {};
    float rsum = 0.f;
    int swa = ((wm + g) >> 1) & 3;
    int swb = ((wn + g) >> 1) & 3;
    int srow = tid & 127, swoff = (tid >> 7) * 8;

    constexpr int NKT = SEQm / BK;              // 32
    stage(0, 0);
    stage(1, BK);
    for (int kt = 0; kt < NKT; kt++) {
        int cur = kt % STAGES;
        if (kt + 2 < NKT) stage((kt + 2) % STAGES, (kt + 2) * BK);
        else              asm volatile("cp.async.commit_group;");
        asm volatile("cp.async.wait_group 2;");
        __syncthreads();

        const uint32_t* Ac = &As32[cur * TA32];
        const uint32_t* Bc = &Bs32[cur * TB32];

        // row-sum from staged bf16 P (phys order = row permutation; full
        // coverage by the two thread halves; fixed order => deterministic)
        {
            const uint32_t* Ar = Ac + srow * 16 + swoff;
            #pragma unroll
            for (int w = 0; w < 8; w++) {
                float2 f = __bfloat1622float2(
                    *reinterpret_cast<const __nv_bfloat162*>(&Ar[w]));
                rsum += f.x + f.y;
            }
        }

        #pragma unroll
        for (int kk = 0; kk < 2; kk++) {
            int p0 = (((kk * 2    ) ^ swa) << 2) | tg;
            int p1 = (((kk * 2 + 1) ^ swa) << 2) | tg;
            int q0 = (((kk * 2    ) ^ swb) << 2) | tg;
            int q1 = (((kk * 2 + 1) ^ swb) << 2) | tg;
            uint32_t af[MI][4];
            uint32_t bf[NI][2];
            #pragma unroll
            for (int mi = 0; mi < MI; mi++) {
                int ra = (wm + mi * 16 + g) * 16;
                af[mi][0] = Ac[ra       + p0];
                af[mi][1] = Ac[ra + 128 + p0];
                af[mi][2] = Ac[ra       + p1];
                af[mi][3] = Ac[ra + 128 + p1];
            }
            #pragma unroll
            for (int ni = 0; ni < NI; ni++) {
                int rb = (wn + ni * 8 + g) * 16;
                bf[ni][0] = Bc[rb + q0];
                bf[ni][1] = Bc[rb + q1];
            }
            #pragma unroll
            for (int mi = 0; mi < MI; mi++)
                #pragma unroll
                for (int ni = 0; ni < NI; ni++)
                    mma_bf16(acc[mi][ni], af[mi], bf[ni]);
        }
        __syncthreads();
    }

    if (tid < 128) ssum[srow] = rsum;
    __syncthreads();
    if (tid >= 128) ssum[srow] += rsum;
    __syncthreads();

    int bb = (int)(z >> 4), hh = (int)(z & 15);
    uint32_t* O32 = (uint32_t*)O;
    #pragma unroll
    for (int mi = 0; mi < MI; mi++) {
        #pragma unroll
        for (int half = 0; half < 2; half++) {
            int ml = wm + mi * 16 + g + half * 8;
            float inv = 1.f / ssum[ml];
            size_t base = ((size_t)bb * SEQm + m0 + ml) * Dm + hh * HDm;
            #pragma unroll
            for (int ni = 0; ni < NI; ni++) {
                int c = wn + ni * 8 + tg * 2;
                O32[(base + c) >> 1] = packbf(acc[mi][ni][half * 2 + 0] * inv,
                                              acc[mi][ni][half * 2 + 1] * inv);
            }
        }
    }
}

// ---------------------------------------------------------------------------
extern "C" void kernel_launch(void* const* d_in, const int* in_sizes, int n_in,
                              void* d_out, int out_size)
{
    const float* x      = (const float*)d_in[0];
    const float* ln1_g  = (const float*)d_in[1];
    const float* ln1_b  = (const float*)d_in[2];
    const float* ln2_g  = (const float*)d_in[3];
    const float* ln2_b  = (const float*)d_in[4];
    const float* qkv_w  = (const float*)d_in[5];
    const float* q_bias = (const float*)d_in[6];
    const float* v_bias = (const float*)d_in[7];
    const float* proj_w = (const float*)d_in[8];
    const float* proj_b = (const float*)d_in[9];
    const float* fc1_w  = (const float*)d_in[10];
    const float* fc1_b  = (const float*)d_in[11];
    const float* fc2_w  = (const float*)d_in[12];
    const float* fc2_b  = (const float*)d_in[13];
    float* out = (float*)d_out;

    __nv_bfloat16 *hb, *qb, *kb, *vtb, *sb, *ob, *gb, *wq, *wp, *w1, *w2;
    float *x1;
    cudaGetSymbolAddress((void**)&hb,  g_hb);
    cudaGetSymbolAddress((void**)&qb,  g_qb);
    cudaGetSymbolAddress((void**)&kb,  g_kb);
    cudaGetSymbolAddress((void**)&vtb, g_vtb);
    cudaGetSymbolAddress((void**)&sb,  g_sb);
    cudaGetSymbolAddress((void**)&ob,  g_ob);
    cudaGetSymbolAddress((void**)&gb,  g_gb);
    cudaGetSymbolAddress((void**)&x1,  g_x1);
    cudaGetSymbolAddress((void**)&wq,  w_qkv);
    cudaGetSymbolAddress((void**)&wp,  w_proj);
    cudaGetSymbolAddress((void**)&w1,  w_fc1);
    cudaGetSymbolAddress((void**)&w2,  w_fc2);

    // 0. weight conversion to bf16
    cvt_kernel<<<(3*Dm*Dm + 255)/256, 256>>>(qkv_w, wq, 3*Dm*Dm);
    cvt_kernel<<<(Dm*Dm   + 255)/256, 256>>>(proj_w, wp, Dm*Dm);
    cvt_kernel<<<(FFm*Dm  + 255)/256, 256>>>(fc1_w, w1, FFm*Dm);
    cvt_kernel<<<(Dm*FFm  + 255)/256, 256>>>(fc2_w, w2, Dm*FFm);

    // 1. LN1 -> bf16
    ln_kernel<<<TOKm, 256>>>(x, ln1_g, ln1_b, hb);

    // 2. QKV = h @ qkv_w^T, fused scatter (q scaled+biased, k, v^T biased)
    tgemm<5><<<dim3(3072/128, TOKm/128, 1), 256>>>(
        hb, wq, nullptr, TOKm, 3*Dm, Dm, 0, 0, 0, q_bias, v_bias);

    // 3. expS[bh] = exp(q @ k^T), bf16 store  (K=64)
    tgemm<6><<<dim3(SEQm/128, SEQm/128, BHm), 256>>>(
        qb, kb, (float*)sb, SEQm, SEQm, HDm,
        (long)SEQm*HDm, (long)SEQm*HDm, (long)SEQm*SEQm, nullptr, nullptr);

    // 4. o = (expS @ v) / rowsum(expS) -> bf16 [b,t,(h,hd)]
    attn_pv<<<dim3(BHm, SEQm/128), 256>>>(sb, vtb, ob);

    // 5. x1 = x + o @ proj_w^T + proj_b  (fp32)
    tgemm<2><<<dim3(Dm/128, TOKm/128, 1), 256>>>(
        ob, wp, x1, TOKm, Dm, Dm, 0, 0, 0, proj_b, x);

    // 6. LN2 -> bf16
    ln_kernel<<<TOKm, 256>>>(x1, ln2_g, ln2_b, hb);

    // 7. g = gelu(h @ fc1_w^T + fc1_b) -> bf16
    tgemm<3><<<dim3(FFm/128, TOKm/128, 1), 256>>>(
        hb, w1, (float*)gb, TOKm, FFm, Dm, 0, 0, 0, fc1_b, nullptr);

    // 8. out = x1 + g @ fc2_w^T + fc2_b  (fp32)
    tgemm<2><<<dim3(Dm/128, TOKm/128, 1), 256>>>(
        gb, w2, out, TOKm, Dm, FFm, 0, 0, 0, fc2_b, x1);
}

// round 14
// speedup vs baseline: 2.9787x; 1.6210x over previous
#include <cuda_runtime.h>
#include <cuda_bf16.h>
#include <math.h>
#include <stdint.h>

#define Dm 1024
#define Hh 16
#define HDm 64
#define FFm 4096
#define BATCHm 8
#define SEQm 1024
#define TOKm (BATCHm*SEQm)   /* 8192 */
#define BHm (BATCHm*Hh)      /* 128  */

static __device__ __nv_bfloat16 g_hb [(size_t)TOKm*Dm];
static __device__ __nv_bfloat16 g_qb [(size_t)BHm*SEQm*HDm];
static __device__ __nv_bfloat16 g_kb [(size_t)BHm*SEQm*HDm];
static __device__ __nv_bfloat16 g_vtb[(size_t)BHm*SEQm*HDm];   // [bh, hd, t]
static __device__ __nv_bfloat16 g_sb [(size_t)BHm*SEQm*SEQm];  // exp(scores) bf16
static __device__ __nv_bfloat16 g_ob [(size_t)TOKm*Dm];
static __device__ __nv_bfloat16 g_gb [(size_t)TOKm*FFm];
static __device__ float         g_x1 [(size_t)TOKm*Dm];
static __device__ __nv_bfloat16 w_qkv[(size_t)3*Dm*Dm];
static __device__ __nv_bfloat16 w_proj[(size_t)Dm*Dm];
static __device__ __nv_bfloat16 w_fc1[(size_t)FFm*Dm];
static __device__ __nv_bfloat16 w_fc2[(size_t)Dm*FFm];

// ---------------------------------------------------------------------------
// helpers
// ---------------------------------------------------------------------------
__device__ __forceinline__ void cp16(uint32_t dst, const void* src) {
    asm volatile("cp.async.cg.shared.global [%0], [%1], 16;" :: "r"(dst), "l"(src));
}
__device__ __forceinline__ void mma_bf16(float* c, const uint32_t* a, const uint32_t* b) {
    asm volatile(
        "mma.sync.aligned.m16n8k16.row.col.f32.bf16.bf16.f32 "
        "{%0,%1,%2,%3},{%4,%5,%6,%7},{%8,%9},{%0,%1,%2,%3};"
        : "+f"(c[0]), "+f"(c[1]), "+f"(c[2]), "+f"(c[3])
        : "r"(a[0]), "r"(a[1]), "r"(a[2]), "r"(a[3]), "r"(b[0]), "r"(b[1]));
}
__device__ __forceinline__ void ldsm4(uint32_t* r, uint32_t addr) {
    asm volatile("ldmatrix.sync.aligned.m8n8.x4.shared.b16 {%0,%1,%2,%3}, [%4];"
                 : "=r"(r[0]), "=r"(r[1]), "=r"(r[2]), "=r"(r[3]) : "r"(addr));
}
__device__ __forceinline__ uint32_t packbf(float lo, float hi) {
    uint32_t r;
    asm("cvt.rn.bf16x2.f32 %0, %1, %2;" : "=r"(r) : "f"(hi), "f"(lo));
    return r;
}

// ---------------------------------------------------------------------------
// fp32 -> bf16 conversion (weights)
// ---------------------------------------------------------------------------
__global__ void cvt_kernel(const float* __restrict__ src,
                           __nv_bfloat16* __restrict__ dst, int n)
{
    int i = blockIdx.x * 256 + threadIdx.x;
    if (i < n) dst[i] = __float2bfloat16_rn(src[i]);
}

// ---------------------------------------------------------------------------
// LayerNorm: fp32 in, bf16 out. One block per row (D=1024).
// ---------------------------------------------------------------------------
__global__ void ln_kernel(const float* __restrict__ x,
                          const float* __restrict__ gam,
                          const float* __restrict__ bet,
                          __nv_bfloat16* __restrict__ out)
{
    const float* xr = x + (size_t)blockIdx.x * Dm;
    __nv_bfloat16* orow = out + (size_t)blockIdx.x * Dm;
    int tid = threadIdx.x;

    float s = 0.f, s2 = 0.f;
    for (int i = tid; i < Dm; i += 256) {
        float v = xr[i];
        s += v; s2 += v * v;
    }
    __shared__ float rs[8], rs2[8];
    #pragma unroll
    for (int o = 16; o > 0; o >>= 1) {
        s  += __shfl_xor_sync(0xffffffffu, s,  o);
        s2 += __shfl_xor_sync(0xffffffffu, s2, o);
    }
    if ((tid & 31) == 0) { rs[tid >> 5] = s; rs2[tid >> 5] = s2; }
    __syncthreads();
    if (tid < 32) {
        float a = (tid < 8) ? rs[tid]  : 0.f;
        float b = (tid < 8) ? rs2[tid] : 0.f;
        #pragma unroll
        for (int o = 4; o > 0; o >>= 1) {
            a += __shfl_xor_sync(0xffffffffu, a, o);
            b += __shfl_xor_sync(0xffffffffu, b, o);
        }
        if (tid == 0) { rs[0] = a; rs2[0] = b; }
    }
    __syncthreads();
    float mu  = rs[0] * (1.0f / Dm);
    float var = rs2[0] * (1.0f / Dm) - mu * mu;
    float inv = rsqrtf(var + 1e-5f);
    for (int i = tid; i < Dm; i += 256)
        orow[i] = __float2bfloat16_rn((xr[i] - mu) * inv * gam[i] + bet[i]);
}

// ---------------------------------------------------------------------------
// bf16 tensor-core GEMM. C = A[M,K] @ B^T (both bf16 row-major K-major).
// BM=BN=128, BK=32, 3-stage cp.async ring (48KB), XOR swizzle (16B chunks).
// Fragment loads via ldmatrix.x4 (conflict-free on the swizzled layout).
// EPI: 2 fp32 bias+residual, 3 bf16 bias+gelu, 5 qkv scatter, 6 bf16 exp.
// ---------------------------------------------------------------------------
template<int EPI>
__global__ __launch_bounds__(256)
void tgemm(const __nv_bfloat16* __restrict__ A, const __nv_bfloat16* __restrict__ B,
           float* __restrict__ C, int M, int N, int K,
           long bA, long bB, long bC,
           const float* __restrict__ bias, const float* __restrict__ res)
{
    constexpr int BM = 128, BN = 128, BK = 32;
    constexpr int MI = 4, NI = 4;               // WM=64, WN=32, 8 warps
    constexpr int STAGES = 3;
    constexpr int TILE32 = BM * 16;             // 2048 u32 per operand stage

    __shared__ alignas(1024) uint32_t As32[STAGES * TILE32];
    __shared__ alignas(1024) uint32_t Bs32[STAGES * TILE32];

    int tid = threadIdx.x, lane = tid & 31, warp = tid >> 5;
    int g = lane >> 2, tg = lane & 3;
    int wm = (warp % 2) * 64, wn = (warp / 2) * 32;
    int m0 = blockIdx.y * BM, n0 = blockIdx.x * BN;
    long z = blockIdx.z;
    const __nv_bfloat16* Ab = A + z * bA;
    const __nv_bfloat16* Bb = B + z * bB;

    uint32_t sA = (uint32_t)__cvta_generic_to_shared(&As32[0]);
    uint32_t sB = (uint32_t)__cvta_generic_to_shared(&Bs32[0]);

    auto stage = [&](int st, int k0) {
        #pragma unroll
        for (int i = tid; i < 512; i += 256) {
            int r = i >> 2, c = i & 3;
            cp16(sA + (uint32_t)((st * TILE32 + r * 16 + ((c ^ ((r >> 1) & 3)) << 2)) * 4),
                 Ab + (size_t)(m0 + r) * K + k0 + c * 8);
        }
        #pragma unroll
        for (int i = tid; i < 512; i += 256) {
            int r = i >> 2, c = i & 3;
            cp16(sB + (uint32_t)((st * TILE32 + r * 16 + ((c ^ ((r >> 1) & 3)) << 2)) * 4),
                 Bb + (size_t)(n0 + r) * K + k0 + c * 8);
        }
        asm volatile("cp.async.commit_group;");
    };

    float acc[MI][NI][4] = {};

    // ldmatrix lane geometry: lanes 0-15 -> rows lr (k-half 0), 16-31 -> k-half 1
    int lr = lane & 15, lh = lane >> 4;
    uint32_t aoff[MI], boff[2];
    int sa[MI], sbw[2];
    #pragma unroll
    for (int mi = 0; mi < MI; mi++) {
        int r = wm + mi * 16 + lr;
        aoff[mi] = (uint32_t)(r * 64);          // row stride 16 u32 = 64 B
        sa[mi] = (r >> 1) & 3;
    }
    #pragma unroll
    for (int p = 0; p < 2; p++) {
        int r = wn + p * 16 + lr;
        boff[p] = (uint32_t)(r * 64);
        sbw[p] = (r >> 1) & 3;
    }

    int NKT = K / BK;
    stage(0, 0);
    stage(1, BK);
    for (int kt = 0; kt < NKT; kt++) {
        int cur = kt % STAGES;
        if (kt + 2 < NKT) stage((kt + 2) % STAGES, (kt + 2) * BK);
        else              asm volatile("cp.async.commit_group;");
        asm volatile("cp.async.wait_group 2;");
        __syncthreads();

        uint32_t AcA = sA + (uint32_t)(cur * TILE32 * 4);
        uint32_t AcB = sB + (uint32_t)(cur * TILE32 * 4);
        #pragma unroll
        for (int kk = 0; kk < 2; kk++) {
            int ch = kk * 2 + lh;
            uint32_t af[MI][4];
            uint32_t bfv[NI][2];
            #pragma unroll
            for (int mi = 0; mi < MI; mi++)
                ldsm4(af[mi], AcA + aoff[mi] + (uint32_t)(((ch ^ sa[mi]) << 4)));
            #pragma unroll
            for (int p = 0; p < 2; p++) {
                uint32_t r4[4];
                ldsm4(r4, AcB + boff[p] + (uint32_t)(((ch ^ sbw[p]) << 4)));
                bfv[2 * p    ][0] = r4[0];
                bfv[2 * p + 1][0] = r4[1];
                bfv[2 * p    ][1] = r4[2];
                bfv[2 * p + 1][1] = r4[3];
            }
            #pragma unroll
            for (int mi = 0; mi < MI; mi++)
                #pragma unroll
                for (int ni = 0; ni < NI; ni++)
                    mma_bf16(acc[mi][ni], af[mi], bfv[ni]);
        }
        __syncthreads();
    }

    // ---- epilogue ----
    #pragma unroll
    for (int mi = 0; mi < MI; mi++) {
        #pragma unroll
        for (int ni = 0; ni < NI; ni++) {
            #pragma unroll
            for (int half = 0; half < 2; half++) {
                int m = m0 + wm + mi * 16 + g + half * 8;
                float v0 = acc[mi][ni][half * 2 + 0];
                float v1 = acc[mi][ni][half * 2 + 1];
                int n = n0 + wn + ni * 8 + tg * 2;
                if (EPI == 2) {
                    float2 w;
                    w.x = v0 + bias[n    ] + res[(size_t)m * N + n    ];
                    w.y = v1 + bias[n + 1] + res[(size_t)m * N + n + 1];
                    *(float2*)&C[(size_t)m * N + n] = w;
                } else if (EPI == 3) {
                    float t0 = v0 + bias[n], t1 = v1 + bias[n + 1];
                    t0 = 0.5f * t0 * (1.f + erff(t0 * 0.70710678118654752f));
                    t1 = 0.5f * t1 * (1.f + erff(t1 * 0.70710678118654752f));
                    ((uint32_t*)C)[((size_t)m * N + n) >> 1] = packbf(t0, t1);
                } else if (EPI == 6) {
                    ((uint32_t*)C)[(z * bC + (size_t)m * N + n) >> 1] =
                        packbf(__expf(v0), __expf(v1));
                } else if (EPI == 5) {
                    #pragma unroll
                    for (int e = 0; e < 2; e++) {
                        float v = e ? v1 : v0;
                        int nn = n + e;
                        int which = nn >> 10;
                        int r = nn & 1023;
                        int hh = r >> 6, hd = r & 63;
                        int bb = m >> 10, t = m & 1023;
                        int bh = bb * Hh + hh;
                        if (which == 0)
                            g_qb[((size_t)bh * SEQm + t) * HDm + hd] =
                                __float2bfloat16_rn((v + bias[r]) * 0.125f);
                        else if (which == 1)
                            g_kb[((size_t)bh * SEQm + t) * HDm + hd] =
                                __float2bfloat16_rn(v);
                        else
                            g_vtb[((size_t)bh * HDm + hd) * SEQm + t] =
                                __float2bfloat16_rn(v + res[r]);
                    }
                }
            }
        }
    }
}

// ---------------------------------------------------------------------------
// attn PV: O[bh] = (P @ Vt^T) / rowsum(P). P bf16 [SEQ,SEQ], Vt bf16 [HD,SEQ].
// bf16 TB-GEMM, BM=128 BN=64 BK=32, 3-stage ring, ldmatrix fragment loads.
// Row sums accumulated fp32 from staged P tiles in fixed order.
// ---------------------------------------------------------------------------
__global__ __launch_bounds__(256)
void attn_pv(const __nv_bfloat16* __restrict__ P, const __nv_bfloat16* __restrict__ V,
             __nv_bfloat16* __restrict__ O)
{
    constexpr int BM = 128, BK = 32;
    constexpr int MI = 2, NI = 4;               // WM=32, WN=32; 4x2 warps
    constexpr int STAGES = 3;
    constexpr int TA32 = BM * 16;
    constexpr int TB32 = 64 * 16;

    __shared__ alignas(1024) uint32_t As32[STAGES * TA32];
    __shared__ alignas(1024) uint32_t Bs32[STAGES * TB32];
    __shared__ float ssum[BM];

    int tid = threadIdx.x, lane = tid & 31, warp = tid >> 5;
    int g = lane >> 2, tg = lane & 3;
    int wm = (warp % 4) * 32, wn = (warp / 4) * 32;
    int m0 = blockIdx.y * BM;
    long z = blockIdx.x;
    const __nv_bfloat16* Ab = P + z * (long)SEQm * SEQm;
    const __nv_bfloat16* Bb = V + z * (long)SEQm * HDm;

    uint32_t sA = (uint32_t)__cvta_generic_to_shared(&As32[0]);
    uint32_t sB = (uint32_t)__cvta_generic_to_shared(&Bs32[0]);

    auto stage = [&](int st, int k0) {
        #pragma unroll
        for (int i = tid; i < 512; i += 256) {
            int r = i >> 2, c = i & 3;
            cp16(sA + (uint32_t)((st * TA32 + r * 16 + ((c ^ ((r >> 1) & 3)) << 2)) * 4),
                 Ab + (size_t)(m0 + r) * SEQm + k0 + c * 8);
        }
        {
            int i = tid;
            if (i < 256) {
                int r = i >> 2, c = i & 3;
                cp16(sB + (uint32_t)((st * TB32 + r * 16 + ((c ^ ((r >> 1) & 3)) << 2)) * 4),
                     Bb + (size_t)r * SEQm + k0 + c * 8);
            }
        }
        asm volatile("cp.async.commit_group;");
    };

    float acc[MI][NI][4] = {};
    float rsum = 0.f;
    int srow = tid & 127, swoff = (tid >> 7) * 8;

    int lr = lane & 15, lh = lane >> 4;
    uint32_t aoff[MI], boff[2];
    int sa[MI], sbw[2];
    #pragma unroll
    for (int mi = 0; mi < MI; mi++) {
        int r = wm + mi * 16 + lr;
        aoff[mi] = (uint32_t)(r * 64);
        sa[mi] = (r >> 1) & 3;
    }
    #pragma unroll
    for (int p = 0; p < 2; p++) {
        int r = wn + p * 16 + lr;
        boff[p] = (uint32_t)(r * 64);
        sbw[p] = (r >> 1) & 3;
    }

    constexpr int NKT = SEQm / BK;
    stage(0, 0);
    stage(1, BK);
    for (int kt = 0; kt < NKT; kt++) {
        int cur = kt % STAGES;
        if (kt + 2 < NKT) stage((kt + 2) % STAGES, (kt + 2) * BK);
        else              asm volatile("cp.async.commit_group;");
        asm volatile("cp.async.wait_group 2;");
        __syncthreads();

        const uint32_t* Ac = &As32[cur * TA32];

        {
            const uint32_t* Ar = Ac + srow * 16 + swoff;
            #pragma unroll
            for (int w = 0; w < 8; w++) {
                float2 f = __bfloat1622float2(
                    *reinterpret_cast<const __nv_bfloat162*>(&Ar[w]));
                rsum += f.x + f.y;
            }
        }

        uint32_t AcA = sA + (uint32_t)(cur * TA32 * 4);
        uint32_t AcB = sB + (uint32_t)(cur * TB32 * 4);
        #pragma unroll
        for (int kk = 0; kk < 2; kk++) {
            int ch = kk * 2 + lh;
            uint32_t af[MI][4];
            uint32_t bfv[NI][2];
            #pragma unroll
            for (int mi = 0; mi < MI; mi++)
                ldsm4(af[mi], AcA + aoff[mi] + (uint32_t)(((ch ^ sa[mi]) << 4)));
            #pragma unroll
            for (int p = 0; p < 2; p++) {
                uint32_t r4[4];
                ldsm4(r4, AcB + boff[p] + (uint32_t)(((ch ^ sbw[p]) << 4)));
                bfv[2 * p    ][0] = r4[0];
                bfv[2 * p + 1][0] = r4[1];
                bfv[2 * p    ][1] = r4[2];
                bfv[2 * p + 1][1] = r4[3];
            }
            #pragma unroll
            for (int mi = 0; mi < MI; mi++)
                #pragma unroll
                for (int ni = 0; ni < NI; ni++)
                    mma_bf16(acc[mi][ni], af[mi], bfv[ni]);
        }
        __syncthreads();
    }

    if (tid < 128) ssum[srow] = rsum;
    __syncthreads();
    if (tid >= 128) ssum[srow] += rsum;
    __syncthreads();

    int bb = (int)(z >> 4), hh = (int)(z & 15);
    uint32_t* O32 = (uint32_t*)O;
    #pragma unroll
    for (int mi = 0; mi < MI; mi++) {
        #pragma unroll
        for (int half = 0; half < 2; half++) {
            int ml = wm + mi * 16 + g + half * 8;
            float inv = 1.f / ssum[ml];
            size_t base = ((size_t)bb * SEQm + m0 + ml) * Dm + hh * HDm;
            #pragma unroll
            for (int ni = 0; ni < NI; ni++) {
                int c = wn + ni * 8 + tg * 2;
                O32[(base + c) >> 1] = packbf(acc[mi][ni][half * 2 + 0] * inv,
                                              acc[mi][ni][half * 2 + 1] * inv);
            }
        }
    }
}

// ---------------------------------------------------------------------------
extern "C" void kernel_launch(void* const* d_in, const int* in_sizes, int n_in,
                              void* d_out, int out_size)
{
    const float* x      = (const float*)d_in[0];
    const float* ln1_g  = (const float*)d_in[1];
    const float* ln1_b  = (const float*)d_in[2];
    const float* ln2_g  = (const float*)d_in[3];
    const float* ln2_b  = (const float*)d_in[4];
    const float* qkv_w  = (const float*)d_in[5];
    const float* q_bias = (const float*)d_in[6];
    const float* v_bias = (const float*)d_in[7];
    const float* proj_w = (const float*)d_in[8];
    const float* proj_b = (const float*)d_in[9];
    const float* fc1_w  = (const float*)d_in[10];
    const float* fc1_b  = (const float*)d_in[11];
    const float* fc2_w  = (const float*)d_in[12];
    const float* fc2_b  = (const float*)d_in[13];
    float* out = (float*)d_out;

    __nv_bfloat16 *hb, *qb, *kb, *vtb, *sb, *ob, *gb, *wq, *wp, *w1, *w2;
    float *x1;
    cudaGetSymbolAddress((void**)&hb,  g_hb);
    cudaGetSymbolAddress((void**)&qb,  g_qb);
    cudaGetSymbolAddress((void**)&kb,  g_kb);
    cudaGetSymbolAddress((void**)&vtb, g_vtb);
    cudaGetSymbolAddress((void**)&sb,  g_sb);
    cudaGetSymbolAddress((void**)&ob,  g_ob);
    cudaGetSymbolAddress((void**)&gb,  g_gb);
    cudaGetSymbolAddress((void**)&x1,  g_x1);
    cudaGetSymbolAddress((void**)&wq,  w_qkv);
    cudaGetSymbolAddress((void**)&wp,  w_proj);
    cudaGetSymbolAddress((void**)&w1,  w_fc1);
    cudaGetSymbolAddress((void**)&w2,  w_fc2);

    // 0. weight conversion to bf16
    cvt_kernel<<<(3*Dm*Dm + 255)/256, 256>>>(qkv_w, wq, 3*Dm*Dm);
    cvt_kernel<<<(Dm*Dm   + 255)/256, 256>>>(proj_w, wp, Dm*Dm);
    cvt_kernel<<<(FFm*Dm  + 255)/256, 256>>>(fc1_w, w1, FFm*Dm);
    cvt_kernel<<<(Dm*FFm  + 255)/256, 256>>>(fc2_w, w2, Dm*FFm);

    // 1. LN1 -> bf16
    ln_kernel<<<TOKm, 256>>>(x, ln1_g, ln1_b, hb);

    // 2. QKV = h @ qkv_w^T, fused scatter (q scaled+biased, k, v^T biased)
    tgemm<5><<<dim3(3072/128, TOKm/128, 1), 256>>>(
        hb, wq, nullptr, TOKm, 3*Dm, Dm, 0, 0, 0, q_bias, v_bias);

    // 3. expS[bh] = exp(q @ k^T), bf16 store  (K=64)
    tgemm<6><<<dim3(SEQm/128, SEQm/128, BHm), 256>>>(
        qb, kb, (float*)sb, SEQm, SEQm, HDm,
        (long)SEQm*HDm, (long)SEQm*HDm, (long)SEQm*SEQm, nullptr, nullptr);

    // 4. o = (expS @ v) / rowsum(expS) -> bf16 [b,t,(h,hd)]
    attn_pv<<<dim3(BHm, SEQm/128), 256>>>(sb, vtb, ob);

    // 5. x1 = x + o @ proj_w^T + proj_b  (fp32)
    tgemm<2><<<dim3(Dm/128, TOKm/128, 1), 256>>>(
        ob, wp, x1, TOKm, Dm, Dm, 0, 0, 0, proj_b, x);

    // 6. LN2 -> bf16
    ln_kernel<<<TOKm, 256>>>(x1, ln2_g, ln2_b, hb);

    // 7. g = gelu(h @ fc1_w^T + fc1_b) -> bf16
    tgemm<3><<<dim3(FFm/128, TOKm/128, 1), 256>>>(
        hb, w1, (float*)gb, TOKm, FFm, Dm, 0, 0, 0, fc1_b, nullptr);

    // 8. out = x1 + g @ fc2_w^T + fc2_b  (fp32)
    tgemm<2><<<dim3(Dm/128, TOKm/128, 1), 256>>>(
        gb, w2, out, TOKm, Dm, FFm, 0, 0, 0, fc2_b, x1);
}

// round 15
// speedup vs baseline: 3.3440x; 1.1226x over previous
#include <cuda_runtime.h>
#include <cuda_bf16.h>
#include <math.h>
#include <stdint.h>

#define Dm 1024
#define Hh 16
#define HDm 64
#define FFm 4096
#define BATCHm 8
#define SEQm 1024
#define TOKm (BATCHm*SEQm)   /* 8192 */
#define BHm (BATCHm*Hh)      /* 128  */

static __device__ __nv_bfloat16 g_hb [(size_t)TOKm*Dm];
static __device__ __nv_bfloat16 g_qb [(size_t)BHm*SEQm*HDm];
static __device__ __nv_bfloat16 g_kb [(size_t)BHm*SEQm*HDm];
static __device__ __nv_bfloat16 g_vtb[(size_t)BHm*SEQm*HDm];   // [bh, hd, t]
static __device__ __nv_bfloat16 g_ob [(size_t)TOKm*Dm];
static __device__ __nv_bfloat16 g_gb [(size_t)TOKm*FFm];
static __device__ float         g_x1 [(size_t)TOKm*Dm];
static __device__ __nv_bfloat16 w_qkv[(size_t)3*Dm*Dm];
static __device__ __nv_bfloat16 w_proj[(size_t)Dm*Dm];
static __device__ __nv_bfloat16 w_fc1[(size_t)FFm*Dm];
static __device__ __nv_bfloat16 w_fc2[(size_t)Dm*FFm];

// ---------------------------------------------------------------------------
// helpers
// ---------------------------------------------------------------------------
__device__ __forceinline__ void cp16(uint32_t dst, const void* src) {
    asm volatile("cp.async.cg.shared.global [%0], [%1], 16;" :: "r"(dst), "l"(src));
}
__device__ __forceinline__ void mma_bf16(float* c, const uint32_t* a, const uint32_t* b) {
    asm volatile(
        "mma.sync.aligned.m16n8k16.row.col.f32.bf16.bf16.f32 "
        "{%0,%1,%2,%3},{%4,%5,%6,%7},{%8,%9},{%0,%1,%2,%3};"
        : "+f"(c[0]), "+f"(c[1]), "+f"(c[2]), "+f"(c[3])
        : "r"(a[0]), "r"(a[1]), "r"(a[2]), "r"(a[3]), "r"(b[0]), "r"(b[1]));
}
__device__ __forceinline__ void ldsm4(uint32_t* r, uint32_t addr) {
    asm volatile("ldmatrix.sync.aligned.m8n8.x4.shared.b16 {%0,%1,%2,%3}, [%4];"
                 : "=r"(r[0]), "=r"(r[1]), "=r"(r[2]), "=r"(r[3]) : "r"(addr));
}
__device__ __forceinline__ uint32_t packbf(float lo, float hi) {
    uint32_t r;
    asm("cvt.rn.bf16x2.f32 %0, %1, %2;" : "=r"(r) : "f"(hi), "f"(lo));
    return r;
}

// ---------------------------------------------------------------------------
// fp32 -> bf16 conversion (weights)
// ---------------------------------------------------------------------------
__global__ void cvt_kernel(const float* __restrict__ src,
                           __nv_bfloat16* __restrict__ dst, int n)
{
    int i = blockIdx.x * 256 + threadIdx.x;
    if (i < n) dst[i] = __float2bfloat16_rn(src[i]);
}

// ---------------------------------------------------------------------------
// LayerNorm: fp32 in, bf16 out. One block per row (D=1024).
// ---------------------------------------------------------------------------
__global__ void ln_kernel(const float* __restrict__ x,
                          const float* __restrict__ gam,
                          const float* __restrict__ bet,
                          __nv_bfloat16* __restrict__ out)
{
    const float* xr = x + (size_t)blockIdx.x * Dm;
    __nv_bfloat16* orow = out + (size_t)blockIdx.x * Dm;
    int tid = threadIdx.x;

    float s = 0.f, s2 = 0.f;
    for (int i = tid; i < Dm; i += 256) {
        float v = xr[i];
        s += v; s2 += v * v;
    }
    __shared__ float rs[8], rs2[8];
    #pragma unroll
    for (int o = 16; o > 0; o >>= 1) {
        s  += __shfl_xor_sync(0xffffffffu, s,  o);
        s2 += __shfl_xor_sync(0xffffffffu, s2, o);
    }
    if ((tid & 31) == 0) { rs[tid >> 5] = s; rs2[tid >> 5] = s2; }
    __syncthreads();
    if (tid < 32) {
        float a = (tid < 8) ? rs[tid]  : 0.f;
        float b = (tid < 8) ? rs2[tid] : 0.f;
        #pragma unroll
        for (int o = 4; o > 0; o >>= 1) {
            a += __shfl_xor_sync(0xffffffffu, a, o);
            b += __shfl_xor_sync(0xffffffffu, b, o);
        }
        if (tid == 0) { rs[0] = a; rs2[0] = b; }
    }
    __syncthreads();
    float mu  = rs[0] * (1.0f / Dm);
    float var = rs2[0] * (1.0f / Dm) - mu * mu;
    float inv = rsqrtf(var + 1e-5f);
    for (int i = tid; i < Dm; i += 256)
        orow[i] = __float2bfloat16_rn((xr[i] - mu) * inv * gam[i] + bet[i]);
}

// ---------------------------------------------------------------------------
// bf16 tensor-core GEMM (R14, unchanged). C = A[M,K] @ B^T.
// ---------------------------------------------------------------------------
template<int EPI>
__global__ __launch_bounds__(256)
void tgemm(const __nv_bfloat16* __restrict__ A, const __nv_bfloat16* __restrict__ B,
           float* __restrict__ C, int M, int N, int K,
           long bA, long bB, long bC,
           const float* __restrict__ bias, const float* __restrict__ res)
{
    constexpr int BM = 128, BN = 128, BK = 32;
    constexpr int MI = 4, NI = 4;
    constexpr int STAGES = 3;
    constexpr int TILE32 = BM * 16;

    __shared__ alignas(1024) uint32_t As32[STAGES * TILE32];
    __shared__ alignas(1024) uint32_t Bs32[STAGES * TILE32];

    int tid = threadIdx.x, lane = tid & 31, warp = tid >> 5;
    int g = lane >> 2, tg = lane & 3;
    int wm = (warp % 2) * 64, wn = (warp / 2) * 32;
    int m0 = blockIdx.y * BM, n0 = blockIdx.x * BN;
    long z = blockIdx.z;
    const __nv_bfloat16* Ab = A + z * bA;
    const __nv_bfloat16* Bb = B + z * bB;

    uint32_t sA = (uint32_t)__cvta_generic_to_shared(&As32[0]);
    uint32_t sB = (uint32_t)__cvta_generic_to_shared(&Bs32[0]);

    auto stage = [&](int st, int k0) {
        #pragma unroll
        for (int i = tid; i < 512; i += 256) {
            int r = i >> 2, c = i & 3;
            cp16(sA + (uint32_t)((st * TILE32 + r * 16 + ((c ^ ((r >> 1) & 3)) << 2)) * 4),
                 Ab + (size_t)(m0 + r) * K + k0 + c * 8);
        }
        #pragma unroll
        for (int i = tid; i < 512; i += 256) {
            int r = i >> 2, c = i & 3;
            cp16(sB + (uint32_t)((st * TILE32 + r * 16 + ((c ^ ((r >> 1) & 3)) << 2)) * 4),
                 Bb + (size_t)(n0 + r) * K + k0 + c * 8);
        }
        asm volatile("cp.async.commit_group;");
    };

    float acc[MI][NI][4] = {};

    int lr = lane & 15, lh = lane >> 4;
    uint32_t aoff[MI], boff[2];
    int sa[MI], sbw[2];
    #pragma unroll
    for (int mi = 0; mi < MI; mi++) {
        int r = wm + mi * 16 + lr;
        aoff[mi] = (uint32_t)(r * 64);
        sa[mi] = (r >> 1) & 3;
    }
    #pragma unroll
    for (int p = 0; p < 2; p++) {
        int r = wn + p * 16 + lr;
        boff[p] = (uint32_t)(r * 64);
        sbw[p] = (r >> 1) & 3;
    }

    int NKT = K / BK;
    stage(0, 0);
    stage(1, BK);
    for (int kt = 0; kt < NKT; kt++) {
        int cur = kt % STAGES;
        if (kt + 2 < NKT) stage((kt + 2) % STAGES, (kt + 2) * BK);
        else              asm volatile("cp.async.commit_group;");
        asm volatile("cp.async.wait_group 2;");
        __syncthreads();

        uint32_t AcA = sA + (uint32_t)(cur * TILE32 * 4);
        uint32_t AcB = sB + (uint32_t)(cur * TILE32 * 4);
        #pragma unroll
        for (int kk = 0; kk < 2; kk++) {
            int ch = kk * 2 + lh;
            uint32_t af[MI][4];
            uint32_t bfv[NI][2];
            #pragma unroll
            for (int mi = 0; mi < MI; mi++)
                ldsm4(af[mi], AcA + aoff[mi] + (uint32_t)(((ch ^ sa[mi]) << 4)));
            #pragma unroll
            for (int p = 0; p < 2; p++) {
                uint32_t r4[4];
                ldsm4(r4, AcB + boff[p] + (uint32_t)(((ch ^ sbw[p]) << 4)));
                bfv[2 * p    ][0] = r4[0];
                bfv[2 * p + 1][0] = r4[1];
                bfv[2 * p    ][1] = r4[2];
                bfv[2 * p + 1][1] = r4[3];
            }
            #pragma unroll
            for (int mi = 0; mi < MI; mi++)
                #pragma unroll
                for (int ni = 0; ni < NI; ni++)
                    mma_bf16(acc[mi][ni], af[mi], bfv[ni]);
        }
        __syncthreads();
    }

    #pragma unroll
    for (int mi = 0; mi < MI; mi++) {
        #pragma unroll
        for (int ni = 0; ni < NI; ni++) {
            #pragma unroll
            for (int half = 0; half < 2; half++) {
                int m = m0 + wm + mi * 16 + g + half * 8;
                float v0 = acc[mi][ni][half * 2 + 0];
                float v1 = acc[mi][ni][half * 2 + 1];
                int n = n0 + wn + ni * 8 + tg * 2;
                if (EPI == 2) {
                    float2 w;
                    w.x = v0 + bias[n    ] + res[(size_t)m * N + n    ];
                    w.y = v1 + bias[n + 1] + res[(size_t)m * N + n + 1];
                    *(float2*)&C[(size_t)m * N + n] = w;
                } else if (EPI == 3) {
                    float t0 = v0 + bias[n], t1 = v1 + bias[n + 1];
                    t0 = 0.5f * t0 * (1.f + erff(t0 * 0.70710678118654752f));
                    t1 = 0.5f * t1 * (1.f + erff(t1 * 0.70710678118654752f));
                    ((uint32_t*)C)[((size_t)m * N + n) >> 1] = packbf(t0, t1);
                } else if (EPI == 5) {
                    #pragma unroll
                    for (int e = 0; e < 2; e++) {
                        float v = e ? v1 : v0;
                        int nn = n + e;
                        int which = nn >> 10;
                        int r = nn & 1023;
                        int hh = r >> 6, hd = r & 63;
                        int bb = m >> 10, t = m & 1023;
                        int bh = bb * Hh + hh;
                        if (which == 0)
                            g_qb[((size_t)bh * SEQm + t) * HDm + hd] =
                                __float2bfloat16_rn((v + bias[r]) * 0.125f);
                        else if (which == 1)
                            g_kb[((size_t)bh * SEQm + t) * HDm + hd] =
                                __float2bfloat16_rn(v);
                        else
                            g_vtb[((size_t)bh * HDm + hd) * SEQm + t] =
                                __float2bfloat16_rn(v + res[r]);
                    }
                }
            }
        }
    }
}

// ---------------------------------------------------------------------------
// Fused attention (no-max softmax): per block 128 q-rows of one bh.
// Q A-frags in registers; 16 K/V tiles of 64 rows, double-buffered.
// P converted acc->A-frag by register packing (zero shuffles).
// Seg-blocked 64B-row smem layout; unit = (r&1)*4 + (c ^ ((r>>1)&3)) ->
// ldmatrix conflict-free. Rowsum over bf16-rounded P (matches R14 numerics).
// ---------------------------------------------------------------------------
__global__ __launch_bounds__(256, 2)
void flash(const __nv_bfloat16* __restrict__ Q, const __nv_bfloat16* __restrict__ K,
           const __nv_bfloat16* __restrict__ Vt, __nv_bfloat16* __restrict__ O)
{
    __shared__ alignas(1024) uint32_t Qs[4096];      // 16KB: 2 segs x 128 rows x 16
    __shared__ alignas(1024) uint32_t Ks[2][2048];   // 8KB/stage: 2 segs x 64 x 16
    __shared__ alignas(1024) uint32_t Vs[2][2048];

    int tid = threadIdx.x, lane = tid & 31, warp = tid >> 5;
    int g = lane >> 2, tg = lane & 3;
    int lr = lane & 15, lh = lane >> 4;
    int wm = warp * 16;
    int q0 = blockIdx.x * 128;
    long z = blockIdx.y;
    const __nv_bfloat16* Qb = Q + (z * SEQm + q0) * HDm;
    const __nv_bfloat16* Kb = K + z * (long)SEQm * HDm;
    const __nv_bfloat16* Vb = Vt + z * (long)SEQm * HDm;   // [hd][t]

    uint32_t sQ = (uint32_t)__cvta_generic_to_shared(&Qs[0]);
    uint32_t sK = (uint32_t)__cvta_generic_to_shared(&Ks[0][0]);
    uint32_t sV = (uint32_t)__cvta_generic_to_shared(&Vs[0][0]);

    // stage Q (group 0)
    #pragma unroll
    for (int i = tid; i < 1024; i += 256) {
        int seg = i >> 9, r = (i >> 2) & 127, c = i & 3;
        cp16(sQ + (uint32_t)((seg * 2048 + r * 16 + ((c ^ ((r >> 1) & 3)) << 2)) * 4),
             Qb + r * HDm + seg * 32 + c * 8);
    }
    asm volatile("cp.async.commit_group;");

    auto stageKV = [&](int st, int t0) {
        #pragma unroll
        for (int i = tid; i < 512; i += 256) {
            int seg = i >> 8, r = (i >> 2) & 63, c = i & 3;
            uint32_t off = (uint32_t)((st * 2048 + seg * 1024 + r * 16 +
                                       ((c ^ ((r >> 1) & 3)) << 2)) * 4);
            cp16(sK + off, Kb + (size_t)(t0 + r) * HDm + seg * 32 + c * 8);
        }
        #pragma unroll
        for (int i = tid; i < 512; i += 256) {
            int seg = i >> 8, r = (i >> 2) & 63, c = i & 3;
            uint32_t off = (uint32_t)((st * 2048 + seg * 1024 + r * 16 +
                                       ((c ^ ((r >> 1) & 3)) << 2)) * 4);
            cp16(sV + off, Vb + (size_t)r * SEQm + t0 + seg * 32 + c * 8);
        }
        asm volatile("cp.async.commit_group;");
    };

    stageKV(0, 0);
    asm volatile("cp.async.wait_group 0;");
    __syncthreads();

    // Q A-frags (held in registers for all tiles)
    uint32_t aq[4][4];
    {
        int rq = wm + lr;
        int swq = (rq >> 1) & 3;
        #pragma unroll
        for (int ch = 0; ch < 4; ch++) {
            int seg = ch >> 1, c16 = (ch & 1) * 2 + lh;
            ldsm4(aq[ch], sQ + (uint32_t)((seg * 2048 + rq * 16 +
                                           ((c16 ^ swq) << 2)) * 4));
        }
    }

    float accO[8][4] = {};
    float rs0 = 0.f, rs1 = 0.f;
    int swb = (((lr) >> 1) & 3);   // row swizzle base for p-loops (rows p*16+lr)

    for (int jt = 0; jt < 16; jt++) {
        if (jt + 1 < 16) stageKV((jt + 1) & 1, (jt + 1) * 64);
        else             asm volatile("cp.async.commit_group;");
        asm volatile("cp.async.wait_group 1;");
        __syncthreads();

        uint32_t bK = sK + (uint32_t)((jt & 1) * 2048 * 4);
        uint32_t bV = sV + (uint32_t)((jt & 1) * 2048 * 4);

        // S = Q @ K^T  (16 x 64 per warp)
        float accS[8][4] = {};
        #pragma unroll
        for (int ch = 0; ch < 4; ch++) {
            int seg = ch >> 1, c16 = (ch & 1) * 2 + lh;
            uint32_t bfv[8][2];
            #pragma unroll
            for (int p = 0; p < 4; p++) {
                int rb = p * 16 + lr;
                uint32_t r4[4];
                ldsm4(r4, bK + (uint32_t)((seg * 1024 + rb * 16 +
                                           ((c16 ^ ((rb >> 1) & 3)) << 2)) * 4));
                bfv[2 * p    ][0] = r4[0];
                bfv[2 * p + 1][0] = r4[1];
                bfv[2 * p    ][1] = r4[2];
                bfv[2 * p + 1][1] = r4[3];
            }
            #pragma unroll
            for (int ni = 0; ni < 8; ni++)
                mma_bf16(accS[ni], aq[ch], bfv[ni]);
        }

        // P = exp(S) packed to A-frags (pure register packing), rowsum of
        // the bf16-rounded values (matches prior pipeline numerics).
        uint32_t ap[4][4];
        #pragma unroll
        for (int t = 0; t < 4; t++) {
            ap[t][0] = packbf(__expf(accS[2*t    ][0]), __expf(accS[2*t    ][1]));
            ap[t][1] = packbf(__expf(accS[2*t    ][2]), __expf(accS[2*t    ][3]));
            ap[t][2] = packbf(__expf(accS[2*t + 1][0]), __expf(accS[2*t + 1][1]));
            ap[t][3] = packbf(__expf(accS[2*t + 1][2]), __expf(accS[2*t + 1][3]));
            float2 f0 = __bfloat1622float2(*(__nv_bfloat162*)&ap[t][0]);
            float2 f2 = __bfloat1622float2(*(__nv_bfloat162*)&ap[t][2]);
            rs0 += (f0.x + f0.y) + (f2.x + f2.y);
            float2 f1 = __bfloat1622float2(*(__nv_bfloat162*)&ap[t][1]);
            float2 f3 = __bfloat1622float2(*(__nv_bfloat162*)&ap[t][3]);
            rs1 += (f1.x + f1.y) + (f3.x + f3.y);
        }

        // O += P @ Vt^T  (16 x 64 per warp; k = 64 kv rows)
        #pragma unroll
        for (int ch = 0; ch < 4; ch++) {
            int seg = ch >> 1, c16 = (ch & 1) * 2 + lh;
            uint32_t bfv[8][2];
            #pragma unroll
            for (int p = 0; p < 4; p++) {
                int rb = p * 16 + lr;
                uint32_t r4[4];
                ldsm4(r4, bV + (uint32_t)((seg * 1024 + rb * 16 +
                                           ((c16 ^ ((rb >> 1) & 3)) << 2)) * 4));
                bfv[2 * p    ][0] = r4[0];
                bfv[2 * p + 1][0] = r4[1];
                bfv[2 * p    ][1] = r4[2];
                bfv[2 * p + 1][1] = r4[3];
            }
            #pragma unroll
            for (int ni = 0; ni < 8; ni++)
                mma_bf16(accO[ni], ap[ch], bfv[ni]);
        }
        __syncthreads();
    }

    // rowsum quad-reduce (cols of a row live on the 4 quad lanes)
    rs0 += __shfl_xor_sync(0xffffffffu, rs0, 1);
    rs0 += __shfl_xor_sync(0xffffffffu, rs0, 2);
    rs1 += __shfl_xor_sync(0xffffffffu, rs1, 1);
    rs1 += __shfl_xor_sync(0xffffffffu, rs1, 2);
    float inv0 = 1.f / rs0, inv1 = 1.f / rs1;

    int bb = (int)(z >> 4), hh = (int)(z & 15);
    uint32_t* O32 = (uint32_t*)O;
    size_t base0 = ((size_t)bb * SEQm + q0 + wm + g) * Dm + hh * HDm;
    size_t base1 = base0 + (size_t)8 * Dm;
    #pragma unroll
    for (int ni = 0; ni < 8; ni++) {
        int c = ni * 8 + tg * 2;
        O32[(base0 + c) >> 1] = packbf(accO[ni][0] * inv0, accO[ni][1] * inv0);
        O32[(base1 + c) >> 1] = packbf(accO[ni][2] * inv1, accO[ni][3] * inv1);
    }
}

// ---------------------------------------------------------------------------
extern "C" void kernel_launch(void* const* d_in, const int* in_sizes, int n_in,
                              void* d_out, int out_size)
{
    const float* x      = (const float*)d_in[0];
    const float* ln1_g  = (const float*)d_in[1];
    const float* ln1_b  = (const float*)d_in[2];
    const float* ln2_g  = (const float*)d_in[3];
    const float* ln2_b  = (const float*)d_in[4];
    const float* qkv_w  = (const float*)d_in[5];
    const float* q_bias = (const float*)d_in[6];
    const float* v_bias = (const float*)d_in[7];
    const float* proj_w = (const float*)d_in[8];
    const float* proj_b = (const float*)d_in[9];
    const float* fc1_w  = (const float*)d_in[10];
    const float* fc1_b  = (const float*)d_in[11];
    const float* fc2_w  = (const float*)d_in[12];
    const float* fc2_b  = (const float*)d_in[13];
    float* out = (float*)d_out;

    __nv_bfloat16 *hb, *qb, *kb, *vtb, *ob, *gb, *wq, *wp, *w1, *w2;
    float *x1;
    cudaGetSymbolAddress((void**)&hb,  g_hb);
    cudaGetSymbolAddress((void**)&qb,  g_qb);
    cudaGetSymbolAddress((void**)&kb,  g_kb);
    cudaGetSymbolAddress((void**)&vtb, g_vtb);
    cudaGetSymbolAddress((void**)&ob,  g_ob);
    cudaGetSymbolAddress((void**)&gb,  g_gb);
    cudaGetSymbolAddress((void**)&x1,  g_x1);
    cudaGetSymbolAddress((void**)&wq,  w_qkv);
    cudaGetSymbolAddress((void**)&wp,  w_proj);
    cudaGetSymbolAddress((void**)&w1,  w_fc1);
    cudaGetSymbolAddress((void**)&w2,  w_fc2);

    // 0. weight conversion to bf16
    cvt_kernel<<<(3*Dm*Dm + 255)/256, 256>>>(qkv_w, wq, 3*Dm*Dm);
    cvt_kernel<<<(Dm*Dm   + 255)/256, 256>>>(proj_w, wp, Dm*Dm);
    cvt_kernel<<<(FFm*Dm  + 255)/256, 256>>>(fc1_w, w1, FFm*Dm);
    cvt_kernel<<<(Dm*FFm  + 255)/256, 256>>>(fc2_w, w2, Dm*FFm);

    // 1. LN1 -> bf16
    ln_kernel<<<TOKm, 256>>>(x, ln1_g, ln1_b, hb);

    // 2. QKV = h @ qkv_w^T, fused scatter (q scaled+biased, k, v^T biased)
    tgemm<5><<<dim3(3072/128, TOKm/128, 1), 256>>>(
        hb, wq, nullptr, TOKm, 3*Dm, Dm, 0, 0, 0, q_bias, v_bias);

    // 3. fused attention: o = softmax(q k^T) v -> bf16 [b,t,(h,hd)]
    flash<<<dim3(SEQm/128, BHm), 256>>>(qb, kb, vtb, ob);

    // 4. x1 = x + o @ proj_w^T + proj_b  (fp32)
    tgemm<2><<<dim3(Dm/128, TOKm/128, 1), 256>>>(
        ob, wp, x1, TOKm, Dm, Dm, 0, 0, 0, proj_b, x);

    // 5. LN2 -> bf16
    ln_kernel<<<TOKm, 256>>>(x1, ln2_g, ln2_b, hb);

    // 6. g = gelu(h @ fc1_w^T + fc1_b) -> bf16
    tgemm<3><<<dim3(FFm/128, TOKm/128, 1), 256>>>(
        hb, w1, (float*)gb, TOKm, FFm, Dm, 0, 0, 0, fc1_b, nullptr);

    // 7. out = x1 + g @ fc2_w^T + fc2_b  (fp32)
    tgemm<2><<<dim3(Dm/128, TOKm/128, 1), 256>>>(
        gb, w2, out, TOKm, Dm, FFm, 0, 0, 0, fc2_b, x1);
}